// round 6
// baseline (speedup 1.0000x reference)
#include <cuda_runtime.h>
#include <cuda_fp16.h>
#include <cstdint>
#include <math.h>

#define BATCH 2048
#define UNITS 1024
#define GATES 4096
#define OUTU 256
#define NCOMB 4352            // [Wc | Wd]
#define STEPS 96
#define K0 1280               // step-0 K: [x | h]
#define LDO (STEPS * OUTU)
#define LOSCALE 2048.0f
#define INV_LOSCALE (1.0f / 2048.0f)

// ------------------------------ device scratch ------------------------------
__device__ __align__(256) float g_Wcd[UNITS * NCOMB];   // fp32 combined weights (non-interleaved)
__device__ __align__(256) float g_bcd[NCOMB];           // combined bias (gate-interleaved + pred)
__device__ __align__(256) float g_b0i[GATES];           // step0 bias b (gate-interleaved)
__device__ __align__(256) float g_c[BATCH * UNITS];     // cell state fp32
__device__ __align__(256) __half g_h0hi[BATCH * UNITS]; // h ping-pong buffers (fp16 hi/lo*2048)
__device__ __align__(256) __half g_h0lo[BATCH * UNITS];
__device__ __align__(256) __half g_h1hi[BATCH * UNITS];
__device__ __align__(256) __half g_h1lo[BATCH * UNITS];
__device__ __align__(256) __half g_wthi[(size_t)NCOMB * UNITS];  // W^T split, interleaved rows
__device__ __align__(256) __half g_wtlo[(size_t)NCOMB * UNITS];
__device__ __align__(256) __half g_w0hi[(size_t)GATES * K0];     // step0 W^T, interleaved rows
__device__ __align__(256) __half g_w0lo[(size_t)GATES * K0];
__device__ __align__(256) __half g_a0hi[(size_t)BATCH * K0];     // step0 A=[x|h]
__device__ __align__(256) __half g_a0lo[(size_t)BATCH * K0];

__device__ __forceinline__ int icol(int n) {            // gate interleave: unit*4+gate
    return (n < GATES) ? ((n & 1023) * 4 + (n >> 10)) : n;
}

// ------------------------------ PTX helpers ---------------------------------
__device__ __forceinline__ uint32_t smem_u32(const void* p) {
    uint32_t a;
    asm("{ .reg .u64 t; cvta.to.shared.u64 t, %1; cvt.u32.u64 %0, t; }" : "=r"(a) : "l"(p));
    return a;
}
__device__ __forceinline__ uint32_t swz(uint32_t off) { return off ^ ((off >> 3) & 0x70); }
__device__ __forceinline__ void cpa16(uint32_t dst, const void* src) {
    asm volatile("cp.async.cg.shared.global [%0], [%1], 16;" :: "r"(dst), "l"(src) : "memory");
}
#define CP_COMMIT()  asm volatile("cp.async.commit_group;" ::: "memory")
#define CP_WAIT(n)   asm volatile("cp.async.wait_group %0;" :: "n"(n) : "memory")

__device__ __forceinline__ void ldsm4(uint32_t* r, uint32_t addr) {
    asm volatile("ldmatrix.sync.aligned.m8n8.x4.shared.b16 {%0,%1,%2,%3}, [%4];"
        : "=r"(r[0]), "=r"(r[1]), "=r"(r[2]), "=r"(r[3]) : "r"(addr));
}
// main: fp16 in, fp32 acc
__device__ __forceinline__ void mma_f32(float* d, const uint32_t* a, uint32_t b0, uint32_t b1) {
    asm volatile("mma.sync.aligned.m16n8k16.row.col.f32.f16.f16.f32 "
        "{%0,%1,%2,%3}, {%4,%5,%6,%7}, {%8,%9}, {%0,%1,%2,%3};"
        : "+f"(d[0]), "+f"(d[1]), "+f"(d[2]), "+f"(d[3])
        : "r"(a[0]), "r"(a[1]), "r"(a[2]), "r"(a[3]), "r"(b0), "r"(b1));
}
// correction: fp16 in, fp16 acc (2x rate)
__device__ __forceinline__ void mma_f16(uint32_t* d, const uint32_t* a, uint32_t b0, uint32_t b1) {
    asm volatile("mma.sync.aligned.m16n8k16.row.col.f16.f16.f16.f16 "
        "{%0,%1}, {%2,%3,%4,%5}, {%6,%7}, {%0,%1};"
        : "+r"(d[0]), "+r"(d[1])
        : "r"(a[0]), "r"(a[1]), "r"(a[2]), "r"(a[3]), "r"(b0), "r"(b1));
}

// ------------------------------ fused split-GEMM + LSTM ----------------------
// C[2048 x Ncols] = A[2048 x K] @ B^T, all operands fp16 hi + (lo*2048).
// acc = hi*hi (fp32) + (hi*lo' + lo'*hi) (fp16 acc) / 2048.
// Block tile 128x128, 512 thr (4x4 warps, 32x32 each), KC=64, 3-stage cp.async,
// single __syncthreads per chunk, prefetch issued after the barrier.
#define KC 64
#define OFF_AHI 0
#define OFF_ALO 16384
#define OFF_BHI 32768
#define OFF_BLO 49152
#define STAGE_BYTES 65536
#define SMEM_TOTAL (3 * STAGE_BYTES)

__device__ __forceinline__ void load_chunk(
    uint32_t sb, int tid,
    const __half* __restrict__ ahi, const __half* __restrict__ alo,
    const __half* __restrict__ bhi, const __half* __restrict__ blo,
    int r0, int n0, int K, int kc)
{
    const int kcol = kc * KC;
    #pragma unroll
    for (int i = 0; i < 2; ++i) {
        int q = tid + i * 512;
        int row = q >> 3, jj = q & 7;              // 128 rows x 8 chunks of 16B
        uint32_t so = swz(row * 128 + jj * 16);
        size_t ga = (size_t)(r0 + row) * K + kcol + jj * 8;
        size_t gb = (size_t)(n0 + row) * K + kcol + jj * 8;
        cpa16(sb + OFF_AHI + so, ahi + ga);
        cpa16(sb + OFF_ALO + so, alo + ga);
        cpa16(sb + OFF_BHI + so, bhi + gb);
        cpa16(sb + OFF_BLO + so, blo + gb);
    }
    CP_COMMIT();
}

__global__ __launch_bounds__(512, 1)
void bgemm(const __half* __restrict__ ahi, const __half* __restrict__ alo,
           const __half* __restrict__ bhi, const __half* __restrict__ blo,
           int K, const float* __restrict__ bias, int n_tile_off, int t,
           float* __restrict__ outp,
           __half* __restrict__ hout_hi, __half* __restrict__ hout_lo)
{
    extern __shared__ __align__(1024) char smem[];
    const uint32_t sbase = smem_u32(smem);
    const int tid = threadIdx.x;
    const int lane = tid & 31, w = tid >> 5;
    const int wm = w & 3, wn = w >> 2;             // 4 (m) x 4 (n) warps
    const int r0 = blockIdx.y * 128;
    const int n0 = (blockIdx.x + n_tile_off) * 128;
    const int nch = K / KC;

    float dm[2][4][4];
    uint32_t dc[2][4][2];
    #pragma unroll
    for (int mi = 0; mi < 2; ++mi)
        #pragma unroll
        for (int nj = 0; nj < 4; ++nj) {
            #pragma unroll
            for (int q = 0; q < 4; ++q) dm[mi][nj][q] = 0.0f;
            dc[mi][nj][0] = 0u; dc[mi][nj][1] = 0u;
        }

    load_chunk(sbase + 0 * STAGE_BYTES, tid, ahi, alo, bhi, blo, r0, n0, K, 0);
    load_chunk(sbase + 1 * STAGE_BYTES, tid, ahi, alo, bhi, blo, r0, n0, K, 1);

    const int lr = lane & 7, sel = lane >> 3;

    for (int kc = 0; kc < nch; ++kc) {
        if (kc < nch - 1) { CP_WAIT(1); } else { CP_WAIT(0); }
        __syncthreads();                            // single barrier per chunk
        if (kc + 2 < nch)
            load_chunk(sbase + ((kc + 2) % 3) * STAGE_BYTES, tid,
                       ahi, alo, bhi, blo, r0, n0, K, kc + 2);
        const uint32_t sb = sbase + (kc % 3) * STAGE_BYTES;

        #pragma unroll
        for (int k16 = 0; k16 < 4; ++k16) {
            // hi fragments, then the 8 main fp32-acc MMAs
            uint32_t ah[2][4], bh[2][4];
            #pragma unroll
            for (int mi = 0; mi < 2; ++mi) {
                int row = wm * 32 + mi * 16 + lr + (sel & 1) * 8;
                int kbe = (k16 * 16 + (sel >> 1) * 8) * 2;
                ldsm4(ah[mi], sb + OFF_AHI + swz(row * 128 + kbe));
            }
            #pragma unroll
            for (int njp = 0; njp < 2; ++njp) {
                int nrow = wn * 32 + njp * 16 + lr + (sel >> 1) * 8;
                int kbe = (k16 * 16 + (sel & 1) * 8) * 2;
                ldsm4(bh[njp], sb + OFF_BHI + swz(nrow * 128 + kbe));
            }
            #pragma unroll
            for (int mi = 0; mi < 2; ++mi)
                #pragma unroll
                for (int nj = 0; nj < 4; ++nj)
                    mma_f32(dm[mi][nj], ah[mi],
                            bh[nj >> 1][(nj & 1) * 2], bh[nj >> 1][(nj & 1) * 2 + 1]);
            // lo fragments load under the main-MMA shadow, then corrections
            uint32_t al[2][4], bl[2][4];
            #pragma unroll
            for (int mi = 0; mi < 2; ++mi) {
                int row = wm * 32 + mi * 16 + lr + (sel & 1) * 8;
                int kbe = (k16 * 16 + (sel >> 1) * 8) * 2;
                ldsm4(al[mi], sb + OFF_ALO + swz(row * 128 + kbe));
            }
            #pragma unroll
            for (int njp = 0; njp < 2; ++njp) {
                int nrow = wn * 32 + njp * 16 + lr + (sel >> 1) * 8;
                int kbe = (k16 * 16 + (sel & 1) * 8) * 2;
                ldsm4(bl[njp], sb + OFF_BLO + swz(nrow * 128 + kbe));
            }
            #pragma unroll
            for (int mi = 0; mi < 2; ++mi)
                #pragma unroll
                for (int nj = 0; nj < 4; ++nj)
                    mma_f16(dc[mi][nj], ah[mi],
                            bl[nj >> 1][(nj & 1) * 2], bl[nj >> 1][(nj & 1) * 2 + 1]);
            #pragma unroll
            for (int mi = 0; mi < 2; ++mi)
                #pragma unroll
                for (int nj = 0; nj < 4; ++nj)
                    mma_f16(dc[mi][nj], al[mi],
                            bh[nj >> 1][(nj & 1) * 2], bh[nj >> 1][(nj & 1) * 2 + 1]);
        }
    }

    // ---------------- epilogue ----------------
    const bool isPred = (n0 >= GATES);
    const int qr = lane >> 2, t4 = lane & 3, qc = t4 * 2;

    #pragma unroll
    for (int mi = 0; mi < 2; ++mi) {
        #pragma unroll
        for (int half = 0; half < 2; ++half) {
            const int r = r0 + wm * 32 + mi * 16 + qr + half * 8;
            #pragma unroll
            for (int nj = 0; nj < 4; ++nj) {
                const int c = wn * 32 + nj * 8 + qc;
                __half2 hc = *reinterpret_cast<__half2*>(&dc[mi][nj][half]);
                float zx = dm[mi][nj][half * 2 + 0]
                         + INV_LOSCALE * __half2float(__low2half(hc)) + bias[n0 + c];
                float zy = dm[mi][nj][half * 2 + 1]
                         + INV_LOSCALE * __half2float(__high2half(hc)) + bias[n0 + c + 1];
                if (isPred) {
                    float2 v = make_float2(zx, zy);
                    *reinterpret_cast<float2*>(
                        outp + (size_t)r * LDO + (size_t)(t - 1) * OUTU + (n0 - GATES) + c) = v;
                } else {
                    // gate-interleaved: even t4 holds (zi,zf), odd holds (zg,zo)
                    float ox = __shfl_xor_sync(0xffffffffu, zx, 1);
                    float oy = __shfl_xor_sync(0xffffffffu, zy, 1);
                    if ((t4 & 1) == 0) {
                        const int u = ((n0 + c) >> 2);
                        const size_t off = (size_t)r * UNITS + u;
                        float ig = 1.0f / (1.0f + expf(-zx));
                        float fg = 1.0f / (1.0f + expf(-zy));
                        float gg = tanhf(ox);
                        float og = 1.0f / (1.0f + expf(-oy));
                        float cn = fg * g_c[off] + ig * gg;
                        g_c[off] = cn;
                        float h = og * tanhf(cn);
                        __half hh = __float2half_rn(h);
                        hout_hi[off] = hh;
                        hout_lo[off] = __float2half_rn((h - __half2float(hh)) * LOSCALE);
                    }
                }
            }
        }
    }
}

// ------------------------------ prep kernels ---------------------------------
__global__ void bias_combine(const float* __restrict__ b,
                             const float* __restrict__ bd,
                             const float* __restrict__ Wk) {
    int j = blockIdx.x * blockDim.x + threadIdx.x;
    if (j < GATES) {
        float s = b[j];
        #pragma unroll 4
        for (int k = 0; k < 256; ++k)
            s += bd[k] * Wk[(size_t)k * GATES + j];
        g_bcd[icol(j)] = s;
        g_b0i[icol(j)] = b[j];
    } else if (j < NCOMB) {
        g_bcd[j] = bd[j - GATES];
    }
}

__global__ void copy_wd(const float* __restrict__ Wd) {
    int idx = blockIdx.x * blockDim.x + threadIdx.x;
    if (idx < UNITS * OUTU) {
        int r = idx / OUTU, c = idx % OUTU;
        g_Wcd[(size_t)r * NCOMB + GATES + c] = Wd[idx];
    }
}

// transpose + interleave + fp16 split: g_Wcd[k][n] -> g_wt{hi,lo}[icol(n)][k]
__global__ void wsplit() {
    int idx = blockIdx.x * blockDim.x + threadIdx.x;   // over UNITS*NCOMB
    int k = idx / NCOMB, n = idx - k * NCOMB;
    float v = g_Wcd[idx];
    __half hi = __float2half_rn(v);
    size_t o = (size_t)icol(n) * UNITS + k;
    g_wthi[o] = hi;
    g_wtlo[o] = __float2half_rn((v - __half2float(hi)) * LOSCALE);
}

// step0 weights: W0^T[icol(n)][k] : k<256 -> Wk[k][n], else Wr[k-256][n]
__global__ void w0split(const float* __restrict__ Wk, const float* __restrict__ Wr) {
    int idx = blockIdx.x * blockDim.x + threadIdx.x;   // over GATES*K0
    int n = idx & (GATES - 1);
    int k = idx >> 12;
    float v = (k < 256) ? Wk[(size_t)k * GATES + n]
                        : Wr[(size_t)(k - 256) * GATES + n];
    __half hi = __float2half_rn(v);
    size_t o = (size_t)icol(n) * K0 + k;
    g_w0hi[o] = hi;
    g_w0lo[o] = __float2half_rn((v - __half2float(hi)) * LOSCALE);
}

// step0 A = [x0 | h0] fp16 split
__global__ void a0split(const float* __restrict__ x0, const float* __restrict__ h0) {
    int idx = blockIdx.x * blockDim.x + threadIdx.x;
    if (idx >= BATCH * K0) return;
    int r = idx / K0, k = idx - r * K0;
    float v = (k < 256) ? x0[(size_t)r * 256 + k] : h0[(size_t)r * UNITS + (k - 256)];
    __half hi = __float2half_rn(v);
    g_a0hi[idx] = hi;
    g_a0lo[idx] = __float2half_rn((v - __half2float(hi)) * LOSCALE);
}

// ------------------------------ fp32 prep GEMM -------------------------------
__global__ __launch_bounds__(256)
void sgemm128(const float* __restrict__ A, int lda,
              const float* __restrict__ B, int ldb, int K,
              const float* __restrict__ Cadd,
              float* __restrict__ C, int ldc) {
    __shared__ float As[8][128];
    __shared__ float Bs[8][128];
    const int tid = threadIdx.x;
    const int tx = tid & 15, ty = tid >> 4;
    const int row0 = blockIdx.y * 128, col0 = blockIdx.x * 128;
    float acc[8][8];
    #pragma unroll
    for (int i = 0; i < 8; ++i)
        #pragma unroll
        for (int j = 0; j < 8; ++j) acc[i][j] = 0.0f;
    const int arow = tid >> 1, acol = (tid & 1) << 2;
    const int brow = tid >> 5, bcol = (tid & 31) << 2;
    const float* Arow = A + (size_t)(row0 + arow) * lda + acol;
    const float* Brow = B + (size_t)brow * ldb + col0 + bcol;
    for (int k0 = 0; k0 < K; k0 += 8) {
        float4 av = *reinterpret_cast<const float4*>(Arow + k0);
        float4 bv = *reinterpret_cast<const float4*>(Brow + (size_t)k0 * ldb);
        As[acol + 0][arow] = av.x; As[acol + 1][arow] = av.y;
        As[acol + 2][arow] = av.z; As[acol + 3][arow] = av.w;
        *reinterpret_cast<float4*>(&Bs[brow][bcol]) = bv;
        __syncthreads();
        #pragma unroll
        for (int k = 0; k < 8; ++k) {
            float a[8], bb[8];
            #pragma unroll
            for (int i = 0; i < 8; ++i) a[i] = As[k][ty * 8 + i];
            #pragma unroll
            for (int j = 0; j < 8; ++j) bb[j] = Bs[k][tx * 8 + j];
            #pragma unroll
            for (int i = 0; i < 8; ++i)
                #pragma unroll
                for (int j = 0; j < 8; ++j)
                    acc[i][j] = fmaf(a[i], bb[j], acc[i][j]);
        }
        __syncthreads();
    }
    const int gcol = col0 + tx * 8;
    #pragma unroll
    for (int i = 0; i < 8; ++i) {
        int r = row0 + ty * 8 + i;
        #pragma unroll
        for (int j = 0; j < 8; j += 4) {
            float4 v = make_float4(acc[i][j], acc[i][j+1], acc[i][j+2], acc[i][j+3]);
            if (Cadd) {
                float4 a4 = *reinterpret_cast<const float4*>(Cadd + (size_t)r * ldb + gcol + j);
                v.x += a4.x; v.y += a4.y; v.z += a4.z; v.w += a4.w;
            }
            *reinterpret_cast<float4*>(C + (size_t)r * ldc + gcol + j) = v;
        }
    }
}

// ------------------------------ launch ---------------------------------------
extern "C" void kernel_launch(void* const* d_in, const int* in_sizes, int n_in,
                              void* d_out, int out_size) {
    const float* x0 = (const float*)d_in[0];
    const float* h0 = (const float*)d_in[1];
    const float* c0 = (const float*)d_in[2];
    const float* Wk = (const float*)d_in[3];
    const float* Wr = (const float*)d_in[4];
    const float* b  = (const float*)d_in[5];
    const float* Wd = (const float*)d_in[6];
    const float* bd = (const float*)d_in[7];
    float* out = (float*)d_out;

    cudaFuncSetAttribute(bgemm, cudaFuncAttributeMaxDynamicSharedMemorySize, SMEM_TOTAL);

    float *pWcd, *pBcd, *pB0i, *pC;
    __half *pWthi, *pWtlo, *pW0hi, *pW0lo, *pA0hi, *pA0lo;
    __half *pH0hi, *pH0lo, *pH1hi, *pH1lo;
    cudaGetSymbolAddress((void**)&pWcd, g_Wcd);
    cudaGetSymbolAddress((void**)&pBcd, g_bcd);
    cudaGetSymbolAddress((void**)&pB0i, g_b0i);
    cudaGetSymbolAddress((void**)&pC, g_c);
    cudaGetSymbolAddress((void**)&pWthi, g_wthi);
    cudaGetSymbolAddress((void**)&pWtlo, g_wtlo);
    cudaGetSymbolAddress((void**)&pW0hi, g_w0hi);
    cudaGetSymbolAddress((void**)&pW0lo, g_w0lo);
    cudaGetSymbolAddress((void**)&pA0hi, g_a0hi);
    cudaGetSymbolAddress((void**)&pA0lo, g_a0lo);
    cudaGetSymbolAddress((void**)&pH0hi, g_h0hi);
    cudaGetSymbolAddress((void**)&pH0lo, g_h0lo);
    cudaGetSymbolAddress((void**)&pH1hi, g_h1hi);
    cudaGetSymbolAddress((void**)&pH1lo, g_h1lo);

    cudaMemcpyAsync(pC, c0, (size_t)BATCH * UNITS * sizeof(float),
                    cudaMemcpyDeviceToDevice, 0);

    // prep
    bias_combine<<<(NCOMB + 255) / 256, 256>>>(b, bd, Wk);
    copy_wd<<<(UNITS * OUTU + 255) / 256, 256>>>(Wd);
    sgemm128<<<dim3(GATES / 128, UNITS / 128), 256>>>(
        Wd, OUTU, Wk, GATES, 256, Wr, pWcd, NCOMB);      // Wc = Wd@Wk + Wr
    wsplit<<<(UNITS * NCOMB) / 256, 256>>>();
    w0split<<<((size_t)GATES * K0) / 256, 256>>>(Wk, Wr);
    a0split<<<(BATCH * K0 + 255) / 256, 256>>>(x0, h0);

    // h buffers: step t reads hb[t&1], writes hb[(t+1)&1]; step0 writes hb[1]
    __half* hhi[2] = {pH0hi, pH1hi};
    __half* hlo[2] = {pH0lo, pH1lo};

    // step 0: gates only (32 tiles), K=1280, fused LSTM -> h1
    bgemm<<<dim3(32, 16), 512, SMEM_TOTAL>>>(
        pA0hi, pA0lo, pW0hi, pW0lo, K0, pB0i, 0, 0, out, hhi[1], hlo[1]);

    // steps 1..95: gates + pred_{t-1} (34 tiles), K=1024
    for (int t = 1; t < STEPS; ++t) {
        bgemm<<<dim3(34, 16), 512, SMEM_TOTAL>>>(
            hhi[t & 1], hlo[t & 1], pWthi, pWtlo, UNITS, pBcd, 0, t, out,
            hhi[(t + 1) & 1], hlo[(t + 1) & 1]);
    }

    // final: pred_95 only (2 pred tiles), reads h_96 = hb[0]
    bgemm<<<dim3(2, 16), 512, SMEM_TOTAL>>>(
        hhi[0], hlo[0], pWthi, pWtlo, UNITS, pBcd, 32, STEPS, out,
        hhi[1], hlo[1]);
}

// round 7
// speedup vs baseline: 1.8059x; 1.8059x over previous
#include <cuda_runtime.h>
#include <cuda_fp16.h>
#include <cstdint>
#include <math.h>

#define BATCH 2048
#define UNITS 1024
#define GATES 4096
#define OUTU 256
#define NCOMB 4352            // [Wc | Wd]
#define STEPS 96
#define K0 1280               // step-0 K: [x | h]
#define LDO (STEPS * OUTU)
#define LOSCALE 2048.0f
#define INV_LOSCALE (1.0f / 2048.0f)

// ------------------------------ device scratch ------------------------------
__device__ __align__(256) float g_Wcd[UNITS * NCOMB];   // fp32 combined weights (non-interleaved)
__device__ __align__(256) float g_bcd[NCOMB];           // combined bias (gate-interleaved + pred)
__device__ __align__(256) float g_b0i[GATES];           // step0 bias b (gate-interleaved)
__device__ __align__(256) float g_c[BATCH * UNITS];     // cell state fp32
__device__ __align__(256) __half g_h0hi[BATCH * UNITS]; // h ping-pong buffers (fp16 hi/lo*2048)
__device__ __align__(256) __half g_h0lo[BATCH * UNITS];
__device__ __align__(256) __half g_h1hi[BATCH * UNITS];
__device__ __align__(256) __half g_h1lo[BATCH * UNITS];
__device__ __align__(256) __half g_wthi[(size_t)NCOMB * UNITS];  // W^T split, interleaved rows
__device__ __align__(256) __half g_wtlo[(size_t)NCOMB * UNITS];
__device__ __align__(256) __half g_w0hi[(size_t)GATES * K0];     // step0 W^T, interleaved rows
__device__ __align__(256) __half g_w0lo[(size_t)GATES * K0];
__device__ __align__(256) __half g_a0hi[(size_t)BATCH * K0];     // step0 A=[x|h]
__device__ __align__(256) __half g_a0lo[(size_t)BATCH * K0];

__device__ __forceinline__ int icol(int n) {            // gate interleave: unit*4+gate
    return (n < GATES) ? ((n & 1023) * 4 + (n >> 10)) : n;
}

// ------------------------------ PTX helpers ---------------------------------
__device__ __forceinline__ uint32_t smem_u32(const void* p) {
    uint32_t a;
    asm("{ .reg .u64 t; cvta.to.shared.u64 t, %1; cvt.u32.u64 %0, t; }" : "=r"(a) : "l"(p));
    return a;
}
__device__ __forceinline__ uint32_t swz(uint32_t off) { return off ^ ((off >> 3) & 0x70); }
__device__ __forceinline__ void cpa16(uint32_t dst, const void* src) {
    asm volatile("cp.async.cg.shared.global [%0], [%1], 16;" :: "r"(dst), "l"(src) : "memory");
}
#define CP_COMMIT()  asm volatile("cp.async.commit_group;" ::: "memory")
#define CP_WAIT(n)   asm volatile("cp.async.wait_group %0;" :: "n"(n) : "memory")

__device__ __forceinline__ void ldsm4(uint32_t* r, uint32_t addr) {
    asm volatile("ldmatrix.sync.aligned.m8n8.x4.shared.b16 {%0,%1,%2,%3}, [%4];"
        : "=r"(r[0]), "=r"(r[1]), "=r"(r[2]), "=r"(r[3]) : "r"(addr));
}
// main: fp16 in, fp32 acc
__device__ __forceinline__ void mma_f32(float* d, const uint32_t* a, uint32_t b0, uint32_t b1) {
    asm volatile("mma.sync.aligned.m16n8k16.row.col.f32.f16.f16.f32 "
        "{%0,%1,%2,%3}, {%4,%5,%6,%7}, {%8,%9}, {%0,%1,%2,%3};"
        : "+f"(d[0]), "+f"(d[1]), "+f"(d[2]), "+f"(d[3])
        : "r"(a[0]), "r"(a[1]), "r"(a[2]), "r"(a[3]), "r"(b0), "r"(b1));
}
// correction: fp16 in, fp16 acc (2x rate)
__device__ __forceinline__ void mma_f16(uint32_t* d, const uint32_t* a, uint32_t b0, uint32_t b1) {
    asm volatile("mma.sync.aligned.m16n8k16.row.col.f16.f16.f16.f16 "
        "{%0,%1}, {%2,%3,%4,%5}, {%6,%7}, {%0,%1};"
        : "+r"(d[0]), "+r"(d[1])
        : "r"(a[0]), "r"(a[1]), "r"(a[2]), "r"(a[3]), "r"(b0), "r"(b1));
}

// ------------------------------ fused split-GEMM + LSTM ----------------------
// C[2048 x Ncols] = A[2048 x K] @ B^T, all operands fp16 hi + (lo*2048).
// acc = hi*hi (fp32) + (hi*lo' + lo'*hi) (fp16 acc) / 2048.
// Block tile 128x128, 512 thr (4x4 warps, 32x32 each), KC=64, 3-stage cp.async.
// R4 chunk-loop skeleton (prefetch BEFORE wait, two syncs per chunk).
// k16 body: hi frags -> main MMAs -> lo frags (hidden) -> correction MMAs.
#define KC 64
#define OFF_AHI 0
#define OFF_ALO 16384
#define OFF_BHI 32768
#define OFF_BLO 49152
#define STAGE_BYTES 65536
#define SMEM_TOTAL (3 * STAGE_BYTES)

__device__ __forceinline__ void load_chunk(
    uint32_t sb, int tid,
    const __half* __restrict__ ahi, const __half* __restrict__ alo,
    const __half* __restrict__ bhi, const __half* __restrict__ blo,
    int r0, int n0, int K, int kc)
{
    const int kcol = kc * KC;
    #pragma unroll
    for (int i = 0; i < 2; ++i) {
        int q = tid + i * 512;
        int row = q >> 3, jj = q & 7;              // 128 rows x 8 chunks of 16B
        uint32_t so = swz(row * 128 + jj * 16);
        size_t ga = (size_t)(r0 + row) * K + kcol + jj * 8;
        size_t gb = (size_t)(n0 + row) * K + kcol + jj * 8;
        cpa16(sb + OFF_AHI + so, ahi + ga);
        cpa16(sb + OFF_ALO + so, alo + ga);
        cpa16(sb + OFF_BHI + so, bhi + gb);
        cpa16(sb + OFF_BLO + so, blo + gb);
    }
    CP_COMMIT();
}

__global__ __launch_bounds__(512, 1)
void bgemm(const __half* __restrict__ ahi, const __half* __restrict__ alo,
           const __half* __restrict__ bhi, const __half* __restrict__ blo,
           int K, const float* __restrict__ bias, int n_tile_off, int t,
           float* __restrict__ outp,
           __half* __restrict__ hout_hi, __half* __restrict__ hout_lo)
{
    extern __shared__ __align__(1024) char smem[];
    const uint32_t sbase = smem_u32(smem);
    const int tid = threadIdx.x;
    const int lane = tid & 31, w = tid >> 5;
    const int wm = w & 3, wn = w >> 2;             // 4 (m) x 4 (n) warps
    const int r0 = blockIdx.y * 128;
    const int n0 = (blockIdx.x + n_tile_off) * 128;
    const int nch = K / KC;

    float dm[2][4][4];
    uint32_t dc[2][4][2];
    #pragma unroll
    for (int mi = 0; mi < 2; ++mi)
        #pragma unroll
        for (int nj = 0; nj < 4; ++nj) {
            #pragma unroll
            for (int q = 0; q < 4; ++q) dm[mi][nj][q] = 0.0f;
            dc[mi][nj][0] = 0u; dc[mi][nj][1] = 0u;
        }

    load_chunk(sbase + 0 * STAGE_BYTES, tid, ahi, alo, bhi, blo, r0, n0, K, 0);
    load_chunk(sbase + 1 * STAGE_BYTES, tid, ahi, alo, bhi, blo, r0, n0, K, 1);

    const int lr = lane & 7, sel = lane >> 3;

    for (int kc = 0; kc < nch; ++kc) {
        if (kc + 2 < nch) {
            load_chunk(sbase + ((kc + 2) % 3) * STAGE_BYTES, tid,
                       ahi, alo, bhi, blo, r0, n0, K, kc + 2);
            CP_WAIT(2);
        } else if (kc + 1 < nch) {
            CP_WAIT(1);
        } else {
            CP_WAIT(0);
        }
        __syncthreads();
        const uint32_t sb = sbase + (kc % 3) * STAGE_BYTES;

        #pragma unroll
        for (int k16 = 0; k16 < 4; ++k16) {
            // hi fragments, then the 8 main fp32-acc MMAs
            uint32_t ah[2][4], bh[2][4];
            #pragma unroll
            for (int mi = 0; mi < 2; ++mi) {
                int row = wm * 32 + mi * 16 + lr + (sel & 1) * 8;
                int kbe = (k16 * 16 + (sel >> 1) * 8) * 2;
                ldsm4(ah[mi], sb + OFF_AHI + swz(row * 128 + kbe));
            }
            #pragma unroll
            for (int njp = 0; njp < 2; ++njp) {
                int nrow = wn * 32 + njp * 16 + lr + (sel >> 1) * 8;
                int kbe = (k16 * 16 + (sel & 1) * 8) * 2;
                ldsm4(bh[njp], sb + OFF_BHI + swz(nrow * 128 + kbe));
            }
            #pragma unroll
            for (int mi = 0; mi < 2; ++mi)
                #pragma unroll
                for (int nj = 0; nj < 4; ++nj)
                    mma_f32(dm[mi][nj], ah[mi],
                            bh[nj >> 1][(nj & 1) * 2], bh[nj >> 1][(nj & 1) * 2 + 1]);
            // lo fragments load under the main-MMA shadow, then corrections
            uint32_t al[2][4], bl[2][4];
            #pragma unroll
            for (int mi = 0; mi < 2; ++mi) {
                int row = wm * 32 + mi * 16 + lr + (sel & 1) * 8;
                int kbe = (k16 * 16 + (sel >> 1) * 8) * 2;
                ldsm4(al[mi], sb + OFF_ALO + swz(row * 128 + kbe));
            }
            #pragma unroll
            for (int njp = 0; njp < 2; ++njp) {
                int nrow = wn * 32 + njp * 16 + lr + (sel >> 1) * 8;
                int kbe = (k16 * 16 + (sel & 1) * 8) * 2;
                ldsm4(bl[njp], sb + OFF_BLO + swz(nrow * 128 + kbe));
            }
            #pragma unroll
            for (int mi = 0; mi < 2; ++mi)
                #pragma unroll
                for (int nj = 0; nj < 4; ++nj)
                    mma_f16(dc[mi][nj], ah[mi],
                            bl[nj >> 1][(nj & 1) * 2], bl[nj >> 1][(nj & 1) * 2 + 1]);
            #pragma unroll
            for (int mi = 0; mi < 2; ++mi)
                #pragma unroll
                for (int nj = 0; nj < 4; ++nj)
                    mma_f16(dc[mi][nj], al[mi],
                            bh[nj >> 1][(nj & 1) * 2], bh[nj >> 1][(nj & 1) * 2 + 1]);
        }
        __syncthreads();
    }

    // ---------------- epilogue ----------------
    const bool isPred = (n0 >= GATES);
    const int qr = lane >> 2, t4 = lane & 3, qc = t4 * 2;

    #pragma unroll
    for (int mi = 0; mi < 2; ++mi) {
        #pragma unroll
        for (int half = 0; half < 2; ++half) {
            const int r = r0 + wm * 32 + mi * 16 + qr + half * 8;
            #pragma unroll
            for (int nj = 0; nj < 4; ++nj) {
                const int c = wn * 32 + nj * 8 + qc;
                __half2 hc = *reinterpret_cast<__half2*>(&dc[mi][nj][half]);
                float zx = dm[mi][nj][half * 2 + 0]
                         + INV_LOSCALE * __half2float(__low2half(hc)) + bias[n0 + c];
                float zy = dm[mi][nj][half * 2 + 1]
                         + INV_LOSCALE * __half2float(__high2half(hc)) + bias[n0 + c + 1];
                if (isPred) {
                    float2 v = make_float2(zx, zy);
                    *reinterpret_cast<float2*>(
                        outp + (size_t)r * LDO + (size_t)(t - 1) * OUTU + (n0 - GATES) + c) = v;
                } else {
                    // gate-interleaved: even t4 holds (zi,zf), odd holds (zg,zo)
                    float ox = __shfl_xor_sync(0xffffffffu, zx, 1);
                    float oy = __shfl_xor_sync(0xffffffffu, zy, 1);
                    if ((t4 & 1) == 0) {
                        const int u = ((n0 + c) >> 2);
                        const size_t off = (size_t)r * UNITS + u;
                        float ig = 1.0f / (1.0f + expf(-zx));
                        float fg = 1.0f / (1.0f + expf(-zy));
                        float gg = tanhf(ox);
                        float og = 1.0f / (1.0f + expf(-oy));
                        float cn = fg * g_c[off] + ig * gg;
                        g_c[off] = cn;
                        float h = og * tanhf(cn);
                        __half hh = __float2half_rn(h);
                        hout_hi[off] = hh;
                        hout_lo[off] = __float2half_rn((h - __half2float(hh)) * LOSCALE);
                    }
                }
            }
        }
    }
}

// ------------------------------ prep kernels ---------------------------------
__global__ void bias_combine(const float* __restrict__ b,
                             const float* __restrict__ bd,
                             const float* __restrict__ Wk) {
    int j = blockIdx.x * blockDim.x + threadIdx.x;
    if (j < GATES) {
        float s = b[j];
        #pragma unroll 4
        for (int k = 0; k < 256; ++k)
            s += bd[k] * Wk[(size_t)k * GATES + j];
        g_bcd[icol(j)] = s;
        g_b0i[icol(j)] = b[j];
    } else if (j < NCOMB) {
        g_bcd[j] = bd[j - GATES];
    }
}

__global__ void copy_wd(const float* __restrict__ Wd) {
    int idx = blockIdx.x * blockDim.x + threadIdx.x;
    if (idx < UNITS * OUTU) {
        int r = idx / OUTU, c = idx % OUTU;
        g_Wcd[(size_t)r * NCOMB + GATES + c] = Wd[idx];
    }
}

// transpose + interleave + fp16 split: g_Wcd[k][n] -> g_wt{hi,lo}[icol(n)][k]
__global__ void wsplit() {
    int idx = blockIdx.x * blockDim.x + threadIdx.x;   // over UNITS*NCOMB
    int k = idx / NCOMB, n = idx - k * NCOMB;
    float v = g_Wcd[idx];
    __half hi = __float2half_rn(v);
    size_t o = (size_t)icol(n) * UNITS + k;
    g_wthi[o] = hi;
    g_wtlo[o] = __float2half_rn((v - __half2float(hi)) * LOSCALE);
}

// step0 weights: W0^T[icol(n)][k] : k<256 -> Wk[k][n], else Wr[k-256][n]
__global__ void w0split(const float* __restrict__ Wk, const float* __restrict__ Wr) {
    int idx = blockIdx.x * blockDim.x + threadIdx.x;   // over GATES*K0
    int n = idx & (GATES - 1);
    int k = idx >> 12;
    float v = (k < 256) ? Wk[(size_t)k * GATES + n]
                        : Wr[(size_t)(k - 256) * GATES + n];
    __half hi = __float2half_rn(v);
    size_t o = (size_t)icol(n) * K0 + k;
    g_w0hi[o] = hi;
    g_w0lo[o] = __float2half_rn((v - __half2float(hi)) * LOSCALE);
}

// step0 A = [x0 | h0] fp16 split
__global__ void a0split(const float* __restrict__ x0, const float* __restrict__ h0) {
    int idx = blockIdx.x * blockDim.x + threadIdx.x;
    if (idx >= BATCH * K0) return;
    int r = idx / K0, k = idx - r * K0;
    float v = (k < 256) ? x0[(size_t)r * 256 + k] : h0[(size_t)r * UNITS + (k - 256)];
    __half hi = __float2half_rn(v);
    g_a0hi[idx] = hi;
    g_a0lo[idx] = __float2half_rn((v - __half2float(hi)) * LOSCALE);
}

// ------------------------------ fp32 prep GEMM -------------------------------
__global__ __launch_bounds__(256)
void sgemm128(const float* __restrict__ A, int lda,
              const float* __restrict__ B, int ldb, int K,
              const float* __restrict__ Cadd,
              float* __restrict__ C, int ldc) {
    __shared__ float As[8][128];
    __shared__ float Bs[8][128];
    const int tid = threadIdx.x;
    const int tx = tid & 15, ty = tid >> 4;
    const int row0 = blockIdx.y * 128, col0 = blockIdx.x * 128;
    float acc[8][8];
    #pragma unroll
    for (int i = 0; i < 8; ++i)
        #pragma unroll
        for (int j = 0; j < 8; ++j) acc[i][j] = 0.0f;
    const int arow = tid >> 1, acol = (tid & 1) << 2;
    const int brow = tid >> 5, bcol = (tid & 31) << 2;
    const float* Arow = A + (size_t)(row0 + arow) * lda + acol;
    const float* Brow = B + (size_t)brow * ldb + col0 + bcol;
    for (int k0 = 0; k0 < K; k0 += 8) {
        float4 av = *reinterpret_cast<const float4*>(Arow + k0);
        float4 bv = *reinterpret_cast<const float4*>(Brow + (size_t)k0 * ldb);
        As[acol + 0][arow] = av.x; As[acol + 1][arow] = av.y;
        As[acol + 2][arow] = av.z; As[acol + 3][arow] = av.w;
        *reinterpret_cast<float4*>(&Bs[brow][bcol]) = bv;
        __syncthreads();
        #pragma unroll
        for (int k = 0; k < 8; ++k) {
            float a[8], bb[8];
            #pragma unroll
            for (int i = 0; i < 8; ++i) a[i] = As[k][ty * 8 + i];
            #pragma unroll
            for (int j = 0; j < 8; ++j) bb[j] = Bs[k][tx * 8 + j];
            #pragma unroll
            for (int i = 0; i < 8; ++i)
                #pragma unroll
                for (int j = 0; j < 8; ++j)
                    acc[i][j] = fmaf(a[i], bb[j], acc[i][j]);
        }
        __syncthreads();
    }
    const int gcol = col0 + tx * 8;
    #pragma unroll
    for (int i = 0; i < 8; ++i) {
        int r = row0 + ty * 8 + i;
        #pragma unroll
        for (int j = 0; j < 8; j += 4) {
            float4 v = make_float4(acc[i][j], acc[i][j+1], acc[i][j+2], acc[i][j+3]);
            if (Cadd) {
                float4 a4 = *reinterpret_cast<const float4*>(Cadd + (size_t)r * ldb + gcol + j);
                v.x += a4.x; v.y += a4.y; v.z += a4.z; v.w += a4.w;
            }
            *reinterpret_cast<float4*>(C + (size_t)r * ldc + gcol + j) = v;
        }
    }
}

// ------------------------------ launch ---------------------------------------
extern "C" void kernel_launch(void* const* d_in, const int* in_sizes, int n_in,
                              void* d_out, int out_size) {
    const float* x0 = (const float*)d_in[0];
    const float* h0 = (const float*)d_in[1];
    const float* c0 = (const float*)d_in[2];
    const float* Wk = (const float*)d_in[3];
    const float* Wr = (const float*)d_in[4];
    const float* b  = (const float*)d_in[5];
    const float* Wd = (const float*)d_in[6];
    const float* bd = (const float*)d_in[7];
    float* out = (float*)d_out;

    cudaFuncSetAttribute(bgemm, cudaFuncAttributeMaxDynamicSharedMemorySize, SMEM_TOTAL);

    float *pWcd, *pBcd, *pB0i, *pC;
    __half *pWthi, *pWtlo, *pW0hi, *pW0lo, *pA0hi, *pA0lo;
    __half *pH0hi, *pH0lo, *pH1hi, *pH1lo;
    cudaGetSymbolAddress((void**)&pWcd, g_Wcd);
    cudaGetSymbolAddress((void**)&pBcd, g_bcd);
    cudaGetSymbolAddress((void**)&pB0i, g_b0i);
    cudaGetSymbolAddress((void**)&pC, g_c);
    cudaGetSymbolAddress((void**)&pWthi, g_wthi);
    cudaGetSymbolAddress((void**)&pWtlo, g_wtlo);
    cudaGetSymbolAddress((void**)&pW0hi, g_w0hi);
    cudaGetSymbolAddress((void**)&pW0lo, g_w0lo);
    cudaGetSymbolAddress((void**)&pA0hi, g_a0hi);
    cudaGetSymbolAddress((void**)&pA0lo, g_a0lo);
    cudaGetSymbolAddress((void**)&pH0hi, g_h0hi);
    cudaGetSymbolAddress((void**)&pH0lo, g_h0lo);
    cudaGetSymbolAddress((void**)&pH1hi, g_h1hi);
    cudaGetSymbolAddress((void**)&pH1lo, g_h1lo);

    cudaMemcpyAsync(pC, c0, (size_t)BATCH * UNITS * sizeof(float),
                    cudaMemcpyDeviceToDevice, 0);

    // prep
    bias_combine<<<(NCOMB + 255) / 256, 256>>>(b, bd, Wk);
    copy_wd<<<(UNITS * OUTU + 255) / 256, 256>>>(Wd);
    sgemm128<<<dim3(GATES / 128, UNITS / 128), 256>>>(
        Wd, OUTU, Wk, GATES, 256, Wr, pWcd, NCOMB);      // Wc = Wd@Wk + Wr
    wsplit<<<(UNITS * NCOMB) / 256, 256>>>();
    w0split<<<((size_t)GATES * K0) / 256, 256>>>(Wk, Wr);
    a0split<<<(BATCH * K0 + 255) / 256, 256>>>(x0, h0);

    // h buffers: step t reads hb[t&1], writes hb[(t+1)&1]; step0 writes hb[1]
    __half* hhi[2] = {pH0hi, pH1hi};
    __half* hlo[2] = {pH0lo, pH1lo};

    // step 0: gates only (32 tiles), K=1280, fused LSTM -> h1
    bgemm<<<dim3(32, 16), 512, SMEM_TOTAL>>>(
        pA0hi, pA0lo, pW0hi, pW0lo, K0, pB0i, 0, 0, out, hhi[1], hlo[1]);

    // steps 1..95: gates + pred_{t-1} (34 tiles), K=1024
    for (int t = 1; t < STEPS; ++t) {
        bgemm<<<dim3(34, 16), 512, SMEM_TOTAL>>>(
            hhi[t & 1], hlo[t & 1], pWthi, pWtlo, UNITS, pBcd, 0, t, out,
            hhi[(t + 1) & 1], hlo[(t + 1) & 1]);
    }

    // final: pred_95 only (2 pred tiles), reads h_96 = hb[0]
    bgemm<<<dim3(2, 16), 512, SMEM_TOTAL>>>(
        hhi[0], hlo[0], pWthi, pWtlo, UNITS, pBcd, 32, STEPS, out,
        hhi[1], hlo[1]);
}

// round 8
// speedup vs baseline: 2.0046x; 1.1100x over previous
#include <cuda_runtime.h>
#include <cuda_fp16.h>
#include <cstdint>
#include <math.h>

#define BATCH 2048
#define UNITS 1024
#define GATES 4096
#define OUTU 256
#define NCOMB 4352            // [Wc | Wd]
#define STEPS 96
#define K0 1280               // step-0 K: [x | h]
#define LDO (STEPS * OUTU)
#define LOSCALE 2048.0f
#define INV_LOSCALE (1.0f / 2048.0f)

// ------------------------------ device scratch ------------------------------
__device__ __align__(256) float g_Wcd[UNITS * NCOMB];   // fp32 combined weights
__device__ __align__(256) float g_bcd[NCOMB];           // combined bias (gate-interleaved + pred)
__device__ __align__(256) float g_b0i[GATES];           // step0 bias (gate-interleaved)
__device__ __align__(256) float g_cf[BATCH * UNITS];    // cell state, FRAGMENT layout
__device__ __align__(256) __half g_h0hi[BATCH * UNITS]; // h ping-pong (fp16 hi/lo*2048)
__device__ __align__(256) __half g_h0lo[BATCH * UNITS];
__device__ __align__(256) __half g_h1hi[BATCH * UNITS];
__device__ __align__(256) __half g_h1lo[BATCH * UNITS];
__device__ __align__(256) __half g_wthi[(size_t)NCOMB * UNITS];  // W^T split, interleaved rows
__device__ __align__(256) __half g_wtlo[(size_t)NCOMB * UNITS];
__device__ __align__(256) __half g_w0hi[(size_t)GATES * K0];     // step0 W^T, interleaved rows
__device__ __align__(256) __half g_w0lo[(size_t)GATES * K0];
__device__ __align__(256) __half g_a0hi[(size_t)BATCH * K0];     // step0 A=[x|h]
__device__ __align__(256) __half g_a0lo[(size_t)BATCH * K0];

__device__ __forceinline__ int icol(int n) {            // gate interleave: unit*4+gate
    return (n < GATES) ? ((n & 1023) * 4 + (n >> 10)) : n;
}

// ------------------------------ PTX helpers ---------------------------------
__device__ __forceinline__ uint32_t smem_u32(const void* p) {
    uint32_t a;
    asm("{ .reg .u64 t; cvta.to.shared.u64 t, %1; cvt.u32.u64 %0, t; }" : "=r"(a) : "l"(p));
    return a;
}
__device__ __forceinline__ uint32_t swz(uint32_t off) { return off ^ ((off >> 3) & 0x70); }
__device__ __forceinline__ void cpa16(uint32_t dst, const void* src) {
    asm volatile("cp.async.cg.shared.global [%0], [%1], 16;" :: "r"(dst), "l"(src) : "memory");
}
#define CP_COMMIT()  asm volatile("cp.async.commit_group;" ::: "memory")
#define CP_WAIT(n)   asm volatile("cp.async.wait_group %0;" :: "n"(n) : "memory")

__device__ __forceinline__ void ldsm4(uint32_t* r, uint32_t addr) {
    asm volatile("ldmatrix.sync.aligned.m8n8.x4.shared.b16 {%0,%1,%2,%3}, [%4];"
        : "=r"(r[0]), "=r"(r[1]), "=r"(r[2]), "=r"(r[3]) : "r"(addr));
}
__device__ __forceinline__ void mma_f32(float* d, const uint32_t* a, uint32_t b0, uint32_t b1) {
    asm volatile("mma.sync.aligned.m16n8k16.row.col.f32.f16.f16.f32 "
        "{%0,%1,%2,%3}, {%4,%5,%6,%7}, {%8,%9}, {%0,%1,%2,%3};"
        : "+f"(d[0]), "+f"(d[1]), "+f"(d[2]), "+f"(d[3])
        : "r"(a[0]), "r"(a[1]), "r"(a[2]), "r"(a[3]), "r"(b0), "r"(b1));
}
__device__ __forceinline__ void mma_f16(uint32_t* d, const uint32_t* a, uint32_t b0, uint32_t b1) {
    asm volatile("mma.sync.aligned.m16n8k16.row.col.f16.f16.f16.f16 "
        "{%0,%1}, {%2,%3,%4,%5}, {%6,%7}, {%0,%1};"
        : "+r"(d[0]), "+r"(d[1])
        : "r"(a[0]), "r"(a[1]), "r"(a[2]), "r"(a[3]), "r"(b0), "r"(b1));
}

// ------------------------------ fused split-GEMM + LSTM ----------------------
// R4-validated skeleton: 128x128 tile, 512 thr (4x4 warps), KC=64, 3-stage
// cp.async, prefetch BEFORE wait, two syncs per chunk.
// Cell state in fragment layout: coalesced float4 in the epilogue.
#define KC 64
#define OFF_AHI 0
#define OFF_ALO 16384
#define OFF_BHI 32768
#define OFF_BLO 49152
#define STAGE_BYTES 65536
#define SMEM_TOTAL (3 * STAGE_BYTES)

__device__ __forceinline__ void load_chunk(
    uint32_t sb, int tid,
    const __half* __restrict__ ahi, const __half* __restrict__ alo,
    const __half* __restrict__ bhi, const __half* __restrict__ blo,
    int r0, int n0, int K, int kc)
{
    const int kcol = kc * KC;
    #pragma unroll
    for (int i = 0; i < 2; ++i) {
        int q = tid + i * 512;
        int row = q >> 3, jj = q & 7;              // 128 rows x 8 chunks of 16B
        uint32_t so = swz(row * 128 + jj * 16);
        size_t ga = (size_t)(r0 + row) * K + kcol + jj * 8;
        size_t gb = (size_t)(n0 + row) * K + kcol + jj * 8;
        cpa16(sb + OFF_AHI + so, ahi + ga);
        cpa16(sb + OFF_ALO + so, alo + ga);
        cpa16(sb + OFF_BHI + so, bhi + gb);
        cpa16(sb + OFF_BLO + so, blo + gb);
    }
    CP_COMMIT();
}

__global__ __launch_bounds__(512, 1)
void bgemm(const __half* __restrict__ ahi, const __half* __restrict__ alo,
           const __half* __restrict__ bhi, const __half* __restrict__ blo,
           int K, const float* __restrict__ bias, int n_tile_off, int t,
           float* __restrict__ outp,
           __half* __restrict__ hout_hi, __half* __restrict__ hout_lo)
{
    extern __shared__ __align__(1024) char smem[];
    const uint32_t sbase = smem_u32(smem);
    const int tid = threadIdx.x;
    const int lane = tid & 31, w = tid >> 5;
    const int wm = w & 3, wn = w >> 2;             // 4 (m) x 4 (n) warps
    const int r0 = blockIdx.y * 128;
    const int n0 = (blockIdx.x + n_tile_off) * 128;
    const int nch = K / KC;

    float dm[2][4][4];
    uint32_t dc[2][4][2];
    #pragma unroll
    for (int mi = 0; mi < 2; ++mi)
        #pragma unroll
        for (int nj = 0; nj < 4; ++nj) {
            #pragma unroll
            for (int q = 0; q < 4; ++q) dm[mi][nj][q] = 0.0f;
            dc[mi][nj][0] = 0u; dc[mi][nj][1] = 0u;
        }

    load_chunk(sbase + 0 * STAGE_BYTES, tid, ahi, alo, bhi, blo, r0, n0, K, 0);
    load_chunk(sbase + 1 * STAGE_BYTES, tid, ahi, alo, bhi, blo, r0, n0, K, 1);

    const int lr = lane & 7, sel = lane >> 3;

    for (int kc = 0; kc < nch; ++kc) {
        if (kc + 2 < nch) {
            load_chunk(sbase + ((kc + 2) % 3) * STAGE_BYTES, tid,
                       ahi, alo, bhi, blo, r0, n0, K, kc + 2);
            CP_WAIT(2);
        } else if (kc + 1 < nch) {
            CP_WAIT(1);
        } else {
            CP_WAIT(0);
        }
        __syncthreads();
        const uint32_t sb = sbase + (kc % 3) * STAGE_BYTES;

        #pragma unroll
        for (int k16 = 0; k16 < 4; ++k16) {
            uint32_t ah[2][4], bh[2][4];
            #pragma unroll
            for (int mi = 0; mi < 2; ++mi) {
                int row = wm * 32 + mi * 16 + lr + (sel & 1) * 8;
                int kbe = (k16 * 16 + (sel >> 1) * 8) * 2;
                ldsm4(ah[mi], sb + OFF_AHI + swz(row * 128 + kbe));
            }
            #pragma unroll
            for (int njp = 0; njp < 2; ++njp) {
                int nrow = wn * 32 + njp * 16 + lr + (sel >> 1) * 8;
                int kbe = (k16 * 16 + (sel & 1) * 8) * 2;
                ldsm4(bh[njp], sb + OFF_BHI + swz(nrow * 128 + kbe));
            }
            #pragma unroll
            for (int mi = 0; mi < 2; ++mi)
                #pragma unroll
                for (int nj = 0; nj < 4; ++nj)
                    mma_f32(dm[mi][nj], ah[mi],
                            bh[nj >> 1][(nj & 1) * 2], bh[nj >> 1][(nj & 1) * 2 + 1]);
            uint32_t al[2][4], bl[2][4];
            #pragma unroll
            for (int mi = 0; mi < 2; ++mi) {
                int row = wm * 32 + mi * 16 + lr + (sel & 1) * 8;
                int kbe = (k16 * 16 + (sel >> 1) * 8) * 2;
                ldsm4(al[mi], sb + OFF_ALO + swz(row * 128 + kbe));
            }
            #pragma unroll
            for (int njp = 0; njp < 2; ++njp) {
                int nrow = wn * 32 + njp * 16 + lr + (sel >> 1) * 8;
                int kbe = (k16 * 16 + (sel & 1) * 8) * 2;
                ldsm4(bl[njp], sb + OFF_BLO + swz(nrow * 128 + kbe));
            }
            #pragma unroll
            for (int mi = 0; mi < 2; ++mi)
                #pragma unroll
                for (int nj = 0; nj < 4; ++nj)
                    mma_f16(dc[mi][nj], ah[mi],
                            bl[nj >> 1][(nj & 1) * 2], bl[nj >> 1][(nj & 1) * 2 + 1]);
            #pragma unroll
            for (int mi = 0; mi < 2; ++mi)
                #pragma unroll
                for (int nj = 0; nj < 4; ++nj)
                    mma_f16(dc[mi][nj], al[mi],
                            bh[nj >> 1][(nj & 1) * 2], bh[nj >> 1][(nj & 1) * 2 + 1]);
        }
        __syncthreads();
    }

    // ---------------- epilogue ----------------
    const bool isPred = (n0 >= GATES);
    const int qr = lane >> 2, t4 = lane & 3, qc = t4 * 2;
    const bool evenT = ((t4 & 1) == 0);
    // fragment-layout c base (valid for gate tiles only: blockIdx.x < 32)
    const int etid = w * 16 + qr * 2 + (t4 >> 1);
    const size_t cbase =
        (((size_t)blockIdx.y * 32 + (size_t)blockIdx.x) * 256 + (size_t)etid) * 16;

    #pragma unroll
    for (int mi = 0; mi < 2; ++mi) {
        #pragma unroll
        for (int half = 0; half < 2; ++half) {
            const int r = r0 + wm * 32 + mi * 16 + qr + half * 8;
            float ca[4];
            if (!isPred && evenT)
                *reinterpret_cast<float4*>(ca) =
                    *reinterpret_cast<float4*>(g_cf + cbase + mi * 8 + half * 4);
            #pragma unroll
            for (int nj = 0; nj < 4; ++nj) {
                const int c = wn * 32 + nj * 8 + qc;
                __half2 hc = *reinterpret_cast<__half2*>(&dc[mi][nj][half]);
                float zx = dm[mi][nj][half * 2 + 0]
                         + INV_LOSCALE * __half2float(__low2half(hc)) + bias[n0 + c];
                float zy = dm[mi][nj][half * 2 + 1]
                         + INV_LOSCALE * __half2float(__high2half(hc)) + bias[n0 + c + 1];
                if (isPred) {
                    float2 v = make_float2(zx, zy);
                    *reinterpret_cast<float2*>(
                        outp + (size_t)r * LDO + (size_t)(t - 1) * OUTU + (n0 - GATES) + c) = v;
                } else {
                    // even t4 holds (zi,zf), odd holds (zg,zo) of the same unit
                    float ox = __shfl_xor_sync(0xffffffffu, zx, 1);
                    float oy = __shfl_xor_sync(0xffffffffu, zy, 1);
                    if (evenT) {
                        const int u = ((n0 + c) >> 2);
                        const size_t off = (size_t)r * UNITS + u;
                        float ig = 1.0f / (1.0f + expf(-zx));
                        float fg = 1.0f / (1.0f + expf(-zy));
                        float gg = tanhf(ox);
                        float og = 1.0f / (1.0f + expf(-oy));
                        float cn = fg * ca[nj] + ig * gg;
                        ca[nj] = cn;
                        float h = og * tanhf(cn);
                        __half hh = __float2half_rn(h);
                        hout_hi[off] = hh;
                        hout_lo[off] = __float2half_rn((h - __half2float(hh)) * LOSCALE);
                    }
                }
            }
            if (!isPred && evenT)
                *reinterpret_cast<float4*>(g_cf + cbase + mi * 8 + half * 4) =
                    *reinterpret_cast<float4*>(ca);
        }
    }
}

// ------------------------------ merged prep 1 --------------------------------
// blocks [0,17): bias_combine; blocks [17, 17+1024): copy_wd
__global__ void prep1(const float* __restrict__ b, const float* __restrict__ bd,
                      const float* __restrict__ Wk, const float* __restrict__ Wd) {
    int blk = blockIdx.x;
    if (blk < 17) {
        int j = blk * 256 + threadIdx.x;
        if (j < GATES) {
            float s = b[j];
            #pragma unroll 4
            for (int k = 0; k < 256; ++k)
                s += bd[k] * Wk[(size_t)k * GATES + j];
            g_bcd[icol(j)] = s;
            g_b0i[icol(j)] = b[j];
        } else if (j < NCOMB) {
            g_bcd[j] = bd[j - GATES];
        }
    } else {
        int idx = (blk - 17) * 256 + threadIdx.x;
        if (idx < UNITS * OUTU) {
            int r = idx / OUTU, c = idx % OUTU;
            g_Wcd[(size_t)r * NCOMB + GATES + c] = Wd[idx];
        }
    }
}

// ------------------------------ merged prep splits ---------------------------
// [0, 17408): wsplit | [17408, 37888): w0split | [37888, 48128): a0split
// [48128, 56320): c_init (canonical c0 -> fragment layout)
#define NB_WS 17408
#define NB_W0 20480
#define NB_A0 10240
#define NB_CI 8192
__global__ void prep_splits(const float* __restrict__ Wk, const float* __restrict__ Wr,
                            const float* __restrict__ x0, const float* __restrict__ h0,
                            const float* __restrict__ c0) {
    int blk = blockIdx.x;
    if (blk < NB_WS) {
        int idx = blk * 256 + threadIdx.x;            // over UNITS*NCOMB
        int k = idx / NCOMB, n = idx - k * NCOMB;
        float v = g_Wcd[idx];
        __half hi = __float2half_rn(v);
        size_t o = (size_t)icol(n) * UNITS + k;
        g_wthi[o] = hi;
        g_wtlo[o] = __float2half_rn((v - __half2float(hi)) * LOSCALE);
    } else if (blk < NB_WS + NB_W0) {
        int idx = (blk - NB_WS) * 256 + threadIdx.x;  // over GATES*K0
        int n = idx & (GATES - 1);
        int k = idx >> 12;
        float v = (k < 256) ? Wk[(size_t)k * GATES + n]
                            : Wr[(size_t)(k - 256) * GATES + n];
        __half hi = __float2half_rn(v);
        size_t o = (size_t)icol(n) * K0 + k;
        g_w0hi[o] = hi;
        g_w0lo[o] = __float2half_rn((v - __half2float(hi)) * LOSCALE);
    } else if (blk < NB_WS + NB_W0 + NB_A0) {
        int idx = (blk - NB_WS - NB_W0) * 256 + threadIdx.x;  // over BATCH*K0
        int r = idx / K0, k = idx - r * K0;
        float v = (k < 256) ? x0[(size_t)r * 256 + k] : h0[(size_t)r * UNITS + (k - 256)];
        __half hi = __float2half_rn(v);
        g_a0hi[idx] = hi;
        g_a0lo[idx] = __float2half_rn((v - __half2float(hi)) * LOSCALE);
    } else {
        int L = (blk - NB_WS - NB_W0 - NB_A0) * 256 + threadIdx.x;  // over BATCH*UNITS
        int mt = L >> 17;            // /(32*256*16)
        int rem = L & 131071;
        int nt = rem >> 12;          // /(256*16)
        int rem2 = rem & 4095;
        int etid = rem2 >> 4, pos = rem2 & 15;
        int ww = etid >> 4, q = etid & 15;
        int qr = q >> 1, th = q & 1;
        int wm = ww & 3, wn = ww >> 2;
        int mi = pos >> 3, half = (pos >> 2) & 1, nj = pos & 3;
        int r = mt * 128 + wm * 32 + mi * 16 + qr + half * 8;
        int u = nt * 32 + wn * 8 + nj * 2 + th;
        g_cf[L] = c0[(size_t)r * UNITS + u];
    }
}

// ------------------------------ fp32 prep GEMM -------------------------------
__global__ __launch_bounds__(256)
void sgemm128(const float* __restrict__ A, int lda,
              const float* __restrict__ B, int ldb, int K,
              const float* __restrict__ Cadd,
              float* __restrict__ C, int ldc) {
    __shared__ float As[8][128];
    __shared__ float Bs[8][128];
    const int tid = threadIdx.x;
    const int tx = tid & 15, ty = tid >> 4;
    const int row0 = blockIdx.y * 128, col0 = blockIdx.x * 128;
    float acc[8][8];
    #pragma unroll
    for (int i = 0; i < 8; ++i)
        #pragma unroll
        for (int j = 0; j < 8; ++j) acc[i][j] = 0.0f;
    const int arow = tid >> 1, acol = (tid & 1) << 2;
    const int brow = tid >> 5, bcol = (tid & 31) << 2;
    const float* Arow = A + (size_t)(row0 + arow) * lda + acol;
    const float* Brow = B + (size_t)brow * ldb + col0 + bcol;
    for (int k0 = 0; k0 < K; k0 += 8) {
        float4 av = *reinterpret_cast<const float4*>(Arow + k0);
        float4 bv = *reinterpret_cast<const float4*>(Brow + (size_t)k0 * ldb);
        As[acol + 0][arow] = av.x; As[acol + 1][arow] = av.y;
        As[acol + 2][arow] = av.z; As[acol + 3][arow] = av.w;
        *reinterpret_cast<float4*>(&Bs[brow][bcol]) = bv;
        __syncthreads();
        #pragma unroll
        for (int k = 0; k < 8; ++k) {
            float a[8], bb[8];
            #pragma unroll
            for (int i = 0; i < 8; ++i) a[i] = As[k][ty * 8 + i];
            #pragma unroll
            for (int j = 0; j < 8; ++j) bb[j] = Bs[k][tx * 8 + j];
            #pragma unroll
            for (int i = 0; i < 8; ++i)
                #pragma unroll
                for (int j = 0; j < 8; ++j)
                    acc[i][j] = fmaf(a[i], bb[j], acc[i][j]);
        }
        __syncthreads();
    }
    const int gcol = col0 + tx * 8;
    #pragma unroll
    for (int i = 0; i < 8; ++i) {
        int r = row0 + ty * 8 + i;
        #pragma unroll
        for (int j = 0; j < 8; j += 4) {
            float4 v = make_float4(acc[i][j], acc[i][j+1], acc[i][j+2], acc[i][j+3]);
            if (Cadd) {
                float4 a4 = *reinterpret_cast<const float4*>(Cadd + (size_t)r * ldb + gcol + j);
                v.x += a4.x; v.y += a4.y; v.z += a4.z; v.w += a4.w;
            }
            *reinterpret_cast<float4*>(C + (size_t)r * ldc + gcol + j) = v;
        }
    }
}

// ------------------------------ launch ---------------------------------------
extern "C" void kernel_launch(void* const* d_in, const int* in_sizes, int n_in,
                              void* d_out, int out_size) {
    const float* x0 = (const float*)d_in[0];
    const float* h0 = (const float*)d_in[1];
    const float* c0 = (const float*)d_in[2];
    const float* Wk = (const float*)d_in[3];
    const float* Wr = (const float*)d_in[4];
    const float* b  = (const float*)d_in[5];
    const float* Wd = (const float*)d_in[6];
    const float* bd = (const float*)d_in[7];
    float* out = (float*)d_out;

    cudaFuncSetAttribute(bgemm, cudaFuncAttributeMaxDynamicSharedMemorySize, SMEM_TOTAL);

    float *pWcd, *pBcd, *pB0i;
    __half *pWthi, *pWtlo, *pW0hi, *pW0lo, *pA0hi, *pA0lo;
    __half *pH0hi, *pH0lo, *pH1hi, *pH1lo;
    cudaGetSymbolAddress((void**)&pWcd, g_Wcd);
    cudaGetSymbolAddress((void**)&pBcd, g_bcd);
    cudaGetSymbolAddress((void**)&pB0i, g_b0i);
    cudaGetSymbolAddress((void**)&pWthi, g_wthi);
    cudaGetSymbolAddress((void**)&pWtlo, g_wtlo);
    cudaGetSymbolAddress((void**)&pW0hi, g_w0hi);
    cudaGetSymbolAddress((void**)&pW0lo, g_w0lo);
    cudaGetSymbolAddress((void**)&pA0hi, g_a0hi);
    cudaGetSymbolAddress((void**)&pA0lo, g_a0lo);
    cudaGetSymbolAddress((void**)&pH0hi, g_h0hi);
    cudaGetSymbolAddress((void**)&pH0lo, g_h0lo);
    cudaGetSymbolAddress((void**)&pH1hi, g_h1hi);
    cudaGetSymbolAddress((void**)&pH1lo, g_h1lo);

    // prep (3 kernels total so ncu's fixed-index capture lands on bgemm)
    prep1<<<17 + 1024, 256>>>(b, bd, Wk, Wd);
    sgemm128<<<dim3(GATES / 128, UNITS / 128), 256>>>(
        Wd, OUTU, Wk, GATES, 256, Wr, pWcd, NCOMB);      // Wc = Wd@Wk + Wr
    prep_splits<<<NB_WS + NB_W0 + NB_A0 + NB_CI, 256>>>(Wk, Wr, x0, h0, c0);

    // h buffers: step t reads hb[t&1], writes hb[(t+1)&1]; step0 writes hb[1]
    __half* hhi[2] = {pH0hi, pH1hi};
    __half* hlo[2] = {pH0lo, pH1lo};

    // step 0: gates only (32 tiles), K=1280, fused LSTM -> h1
    bgemm<<<dim3(32, 16), 512, SMEM_TOTAL>>>(
        pA0hi, pA0lo, pW0hi, pW0lo, K0, pB0i, 0, 0, out, hhi[1], hlo[1]);

    // steps 1..95: gates + pred_{t-1} (34 tiles), K=1024
    for (int t = 1; t < STEPS; ++t) {
        bgemm<<<dim3(34, 16), 512, SMEM_TOTAL>>>(
            hhi[t & 1], hlo[t & 1], pWthi, pWtlo, UNITS, pBcd, 0, t, out,
            hhi[(t + 1) & 1], hlo[(t + 1) & 1]);
    }

    // final: pred_95 only (2 pred tiles), reads h_96 = hb[0]
    bgemm<<<dim3(2, 16), 512, SMEM_TOTAL>>>(
        hhi[0], hlo[0], pWthi, pWtlo, UNITS, pBcd, 32, STEPS, out,
        hhi[1], hlo[1]);
}

// round 9
// speedup vs baseline: 2.2267x; 1.1108x over previous
#include <cuda_runtime.h>
#include <cuda_fp16.h>
#include <cstdint>
#include <math.h>

#define BATCH 2048
#define UNITS 1024
#define GATES 4096
#define OUTU 256
#define NCOMB 4352            // [Wc | Wd]
#define STEPS 96
#define K0 1280               // step-0 K: [x | h]
#define LDO (STEPS * OUTU)
#define LOSCALE 2048.0f
#define INV_LOSCALE (1.0f / 2048.0f)

// ------------------------------ device scratch ------------------------------
__device__ __align__(256) float g_Wcd[UNITS * NCOMB];   // fp32 combined weights
__device__ __align__(256) float g_bcd[NCOMB];           // combined bias (gate-interleaved + pred)
__device__ __align__(256) float g_b0i[GATES];           // step0 bias (gate-interleaved)
__device__ __align__(256) float g_cf[BATCH * UNITS];    // cell state, FRAGMENT layout
__device__ __align__(256) __half g_h0hi[BATCH * UNITS]; // h ping-pong (fp16 hi/lo*2048)
__device__ __align__(256) __half g_h0lo[BATCH * UNITS];
__device__ __align__(256) __half g_h1hi[BATCH * UNITS];
__device__ __align__(256) __half g_h1lo[BATCH * UNITS];
__device__ __align__(256) __half g_wthi[(size_t)NCOMB * UNITS];  // W^T split, interleaved rows
__device__ __align__(256) __half g_wtlo[(size_t)NCOMB * UNITS];
__device__ __align__(256) __half g_w0hi[(size_t)GATES * K0];     // step0 W^T, interleaved rows
__device__ __align__(256) __half g_w0lo[(size_t)GATES * K0];
__device__ __align__(256) __half g_a0hi[(size_t)BATCH * K0];     // step0 A=[x|h]
__device__ __align__(256) __half g_a0lo[(size_t)BATCH * K0];

__device__ __forceinline__ int icol(int n) {            // gate interleave: unit*4+gate
    return (n < GATES) ? ((n & 1023) * 4 + (n >> 10)) : n;
}

// ------------------------------ PTX helpers ---------------------------------
__device__ __forceinline__ uint32_t smem_u32(const void* p) {
    uint32_t a;
    asm("{ .reg .u64 t; cvta.to.shared.u64 t, %1; cvt.u32.u64 %0, t; }" : "=r"(a) : "l"(p));
    return a;
}
__device__ __forceinline__ uint32_t swz(uint32_t off) { return off ^ ((off >> 3) & 0x70); }
__device__ __forceinline__ void cpa16(uint32_t dst, const void* src) {
    asm volatile("cp.async.cg.shared.global [%0], [%1], 16;" :: "r"(dst), "l"(src) : "memory");
}
#define CP_COMMIT()  asm volatile("cp.async.commit_group;" ::: "memory")
#define CP_WAIT(n)   asm volatile("cp.async.wait_group %0;" :: "n"(n) : "memory")

__device__ __forceinline__ void ldsm4(uint32_t* r, uint32_t addr) {
    asm volatile("ldmatrix.sync.aligned.m8n8.x4.shared.b16 {%0,%1,%2,%3}, [%4];"
        : "=r"(r[0]), "=r"(r[1]), "=r"(r[2]), "=r"(r[3]) : "r"(addr));
}
__device__ __forceinline__ void mma_f32(float* d, const uint32_t* a, uint32_t b0, uint32_t b1) {
    asm volatile("mma.sync.aligned.m16n8k16.row.col.f32.f16.f16.f32 "
        "{%0,%1,%2,%3}, {%4,%5,%6,%7}, {%8,%9}, {%0,%1,%2,%3};"
        : "+f"(d[0]), "+f"(d[1]), "+f"(d[2]), "+f"(d[3])
        : "r"(a[0]), "r"(a[1]), "r"(a[2]), "r"(a[3]), "r"(b0), "r"(b1));
}
__device__ __forceinline__ void mma_f16(uint32_t* d, const uint32_t* a, uint32_t b0, uint32_t b1) {
    asm volatile("mma.sync.aligned.m16n8k16.row.col.f16.f16.f16.f16 "
        "{%0,%1}, {%2,%3,%4,%5}, {%6,%7}, {%0,%1};"
        : "+r"(d[0]), "+r"(d[1])
        : "r"(a[0]), "r"(a[1]), "r"(a[2]), "r"(a[3]), "r"(b0), "r"(b1));
}

// ------------------------------ fused split-GEMM + LSTM ----------------------
// Tile 128(M)x64(N), 256 thr (8 warps as 4m x 2n, 32x32 each), KC=64,
// 2-stage cp.async pipeline -> 96KB smem/CTA, 2 CTAs/SM co-residency.
#define KC 64
#define OFF_AHI 0
#define OFF_ALO 16384
#define OFF_BHI 32768
#define OFF_BLO 40960
#define STAGE_BYTES 49152
#define SMEM_TOTAL (2 * STAGE_BYTES)

__device__ __forceinline__ void load_chunk(
    uint32_t sb, int tid,
    const __half* __restrict__ ahi, const __half* __restrict__ alo,
    const __half* __restrict__ bhi, const __half* __restrict__ blo,
    int r0, int n0, int K, int kc)
{
    const int kcol = kc * KC;
    #pragma unroll
    for (int i = 0; i < 4; ++i) {              // A: 128 rows x 8 chunks of 16B
        int q = tid + i * 256;
        int row = q >> 3, jj = q & 7;
        uint32_t so = swz(row * 128 + jj * 16);
        size_t ga = (size_t)(r0 + row) * K + kcol + jj * 8;
        cpa16(sb + OFF_AHI + so, ahi + ga);
        cpa16(sb + OFF_ALO + so, alo + ga);
    }
    #pragma unroll
    for (int i = 0; i < 2; ++i) {              // B: 64 rows x 8 chunks of 16B
        int q = tid + i * 256;
        int row = q >> 3, jj = q & 7;
        uint32_t so = swz(row * 128 + jj * 16);
        size_t gb = (size_t)(n0 + row) * K + kcol + jj * 8;
        cpa16(sb + OFF_BHI + so, bhi + gb);
        cpa16(sb + OFF_BLO + so, blo + gb);
    }
    CP_COMMIT();
}

__global__ __launch_bounds__(256, 2)
void bgemm(const __half* __restrict__ ahi, const __half* __restrict__ alo,
           const __half* __restrict__ bhi, const __half* __restrict__ blo,
           int K, const float* __restrict__ bias, int n_tile_off, int t,
           float* __restrict__ outp,
           __half* __restrict__ hout_hi, __half* __restrict__ hout_lo)
{
    extern __shared__ __align__(1024) char smem[];
    const uint32_t sbase = smem_u32(smem);
    const int tid = threadIdx.x;
    const int lane = tid & 31, w = tid >> 5;
    const int wm = w & 3, wn = w >> 2;             // 4 (m) x 2 (n) warps
    const int r0 = blockIdx.y * 128;
    const int n0 = (blockIdx.x + n_tile_off) * 64;
    const int nch = K / KC;

    float dm[2][4][4];
    uint32_t dc[2][4][2];
    #pragma unroll
    for (int mi = 0; mi < 2; ++mi)
        #pragma unroll
        for (int nj = 0; nj < 4; ++nj) {
            #pragma unroll
            for (int q = 0; q < 4; ++q) dm[mi][nj][q] = 0.0f;
            dc[mi][nj][0] = 0u; dc[mi][nj][1] = 0u;
        }

    load_chunk(sbase + 0 * STAGE_BYTES, tid, ahi, alo, bhi, blo, r0, n0, K, 0);
    load_chunk(sbase + 1 * STAGE_BYTES, tid, ahi, alo, bhi, blo, r0, n0, K, 1);

    const int lr = lane & 7, sel = lane >> 3;

    for (int kc = 0; kc < nch; ++kc) {
        if (kc + 1 < nch) { CP_WAIT(1); } else { CP_WAIT(0); }
        __syncthreads();
        const uint32_t sb = sbase + (kc & 1) * STAGE_BYTES;

        #pragma unroll
        for (int k16 = 0; k16 < 4; ++k16) {
            uint32_t ah[2][4], bh[2][4];
            #pragma unroll
            for (int mi = 0; mi < 2; ++mi) {
                int row = wm * 32 + mi * 16 + lr + (sel & 1) * 8;
                int kbe = (k16 * 16 + (sel >> 1) * 8) * 2;
                ldsm4(ah[mi], sb + OFF_AHI + swz(row * 128 + kbe));
            }
            #pragma unroll
            for (int njp = 0; njp < 2; ++njp) {
                int nrow = wn * 32 + njp * 16 + lr + (sel >> 1) * 8;
                int kbe = (k16 * 16 + (sel & 1) * 8) * 2;
                ldsm4(bh[njp], sb + OFF_BHI + swz(nrow * 128 + kbe));
            }
            #pragma unroll
            for (int mi = 0; mi < 2; ++mi)
                #pragma unroll
                for (int nj = 0; nj < 4; ++nj)
                    mma_f32(dm[mi][nj], ah[mi],
                            bh[nj >> 1][(nj & 1) * 2], bh[nj >> 1][(nj & 1) * 2 + 1]);
            uint32_t al[2][4], bl[2][4];
            #pragma unroll
            for (int mi = 0; mi < 2; ++mi) {
                int row = wm * 32 + mi * 16 + lr + (sel & 1) * 8;
                int kbe = (k16 * 16 + (sel >> 1) * 8) * 2;
                ldsm4(al[mi], sb + OFF_ALO + swz(row * 128 + kbe));
            }
            #pragma unroll
            for (int njp = 0; njp < 2; ++njp) {
                int nrow = wn * 32 + njp * 16 + lr + (sel >> 1) * 8;
                int kbe = (k16 * 16 + (sel & 1) * 8) * 2;
                ldsm4(bl[njp], sb + OFF_BLO + swz(nrow * 128 + kbe));
            }
            #pragma unroll
            for (int mi = 0; mi < 2; ++mi)
                #pragma unroll
                for (int nj = 0; nj < 4; ++nj)
                    mma_f16(dc[mi][nj], ah[mi],
                            bl[nj >> 1][(nj & 1) * 2], bl[nj >> 1][(nj & 1) * 2 + 1]);
            #pragma unroll
            for (int mi = 0; mi < 2; ++mi)
                #pragma unroll
                for (int nj = 0; nj < 4; ++nj)
                    mma_f16(dc[mi][nj], al[mi],
                            bh[nj >> 1][(nj & 1) * 2], bh[nj >> 1][(nj & 1) * 2 + 1]);
        }
        __syncthreads();
        if (kc + 2 < nch)
            load_chunk(sbase + (kc & 1) * STAGE_BYTES, tid,
                       ahi, alo, bhi, blo, r0, n0, K, kc + 2);
    }

    // ---------------- epilogue ----------------
    const bool isPred = (n0 >= GATES);
    const int qr = lane >> 2, t4 = lane & 3, qc = t4 * 2;
    const bool evenT = ((t4 & 1) == 0);
    // fragment-layout c base (gate tiles only: blockIdx.x < 64)
    const int etid = w * 16 + qr * 2 + (t4 >> 1);            // [0,128)
    const size_t cbase =
        (((size_t)blockIdx.y * 64 + (size_t)blockIdx.x) * 128 + (size_t)etid) * 16;

    #pragma unroll
    for (int mi = 0; mi < 2; ++mi) {
        #pragma unroll
        for (int half = 0; half < 2; ++half) {
            const int r = r0 + wm * 32 + mi * 16 + qr + half * 8;
            float ca[4];
            if (!isPred && evenT)
                *reinterpret_cast<float4*>(ca) =
                    *reinterpret_cast<float4*>(g_cf + cbase + mi * 8 + half * 4);
            #pragma unroll
            for (int nj = 0; nj < 4; ++nj) {
                const int c = wn * 32 + nj * 8 + qc;
                __half2 hc = *reinterpret_cast<__half2*>(&dc[mi][nj][half]);
                float zx = dm[mi][nj][half * 2 + 0]
                         + INV_LOSCALE * __half2float(__low2half(hc)) + bias[n0 + c];
                float zy = dm[mi][nj][half * 2 + 1]
                         + INV_LOSCALE * __half2float(__high2half(hc)) + bias[n0 + c + 1];
                if (isPred) {
                    float2 v = make_float2(zx, zy);
                    *reinterpret_cast<float2*>(
                        outp + (size_t)r * LDO + (size_t)(t - 1) * OUTU + (n0 - GATES) + c) = v;
                } else {
                    // even t4 holds (zi,zf), odd holds (zg,zo) of the same unit
                    float ox = __shfl_xor_sync(0xffffffffu, zx, 1);
                    float oy = __shfl_xor_sync(0xffffffffu, zy, 1);
                    if (evenT) {
                        const int u = ((n0 + c) >> 2);
                        const size_t off = (size_t)r * UNITS + u;
                        float ig = 1.0f / (1.0f + expf(-zx));
                        float fg = 1.0f / (1.0f + expf(-zy));
                        float gg = tanhf(ox);
                        float og = 1.0f / (1.0f + expf(-oy));
                        float cn = fg * ca[nj] + ig * gg;
                        ca[nj] = cn;
                        float h = og * tanhf(cn);
                        __half hh = __float2half_rn(h);
                        hout_hi[off] = hh;
                        hout_lo[off] = __float2half_rn((h - __half2float(hh)) * LOSCALE);
                    }
                }
            }
            if (!isPred && evenT)
                *reinterpret_cast<float4*>(g_cf + cbase + mi * 8 + half * 4) =
                    *reinterpret_cast<float4*>(ca);
        }
    }
}

// ------------------------------ merged prep 1 --------------------------------
__global__ void prep1(const float* __restrict__ b, const float* __restrict__ bd,
                      const float* __restrict__ Wk, const float* __restrict__ Wd) {
    int blk = blockIdx.x;
    if (blk < 17) {
        int j = blk * 256 + threadIdx.x;
        if (j < GATES) {
            float s = b[j];
            #pragma unroll 4
            for (int k = 0; k < 256; ++k)
                s += bd[k] * Wk[(size_t)k * GATES + j];
            g_bcd[icol(j)] = s;
            g_b0i[icol(j)] = b[j];
        } else if (j < NCOMB) {
            g_bcd[j] = bd[j - GATES];
        }
    } else {
        int idx = (blk - 17) * 256 + threadIdx.x;
        if (idx < UNITS * OUTU) {
            int r = idx / OUTU, c = idx % OUTU;
            g_Wcd[(size_t)r * NCOMB + GATES + c] = Wd[idx];
        }
    }
}

// ------------------------------ merged prep splits ---------------------------
// [0, NB_WS): wsplit | [.., +NB_W0): w0split | [.., +NB_A0): a0split
// [.., +NB_CI): c_init (canonical c0 -> fragment layout, 128x64 tiles)
#define NB_WS 17408
#define NB_W0 20480
#define NB_A0 10240
#define NB_CI 8192
__global__ void prep_splits(const float* __restrict__ Wk, const float* __restrict__ Wr,
                            const float* __restrict__ x0, const float* __restrict__ h0,
                            const float* __restrict__ c0) {
    int blk = blockIdx.x;
    if (blk < NB_WS) {
        int idx = blk * 256 + threadIdx.x;            // over UNITS*NCOMB
        int k = idx / NCOMB, n = idx - k * NCOMB;
        float v = g_Wcd[idx];
        __half hi = __float2half_rn(v);
        size_t o = (size_t)icol(n) * UNITS + k;
        g_wthi[o] = hi;
        g_wtlo[o] = __float2half_rn((v - __half2float(hi)) * LOSCALE);
    } else if (blk < NB_WS + NB_W0) {
        int idx = (blk - NB_WS) * 256 + threadIdx.x;  // over GATES*K0
        int n = idx & (GATES - 1);
        int k = idx >> 12;
        float v = (k < 256) ? Wk[(size_t)k * GATES + n]
                            : Wr[(size_t)(k - 256) * GATES + n];
        __half hi = __float2half_rn(v);
        size_t o = (size_t)icol(n) * K0 + k;
        g_w0hi[o] = hi;
        g_w0lo[o] = __float2half_rn((v - __half2float(hi)) * LOSCALE);
    } else if (blk < NB_WS + NB_W0 + NB_A0) {
        int idx = (blk - NB_WS - NB_W0) * 256 + threadIdx.x;  // over BATCH*K0
        int r = idx / K0, k = idx - r * K0;
        float v = (k < 256) ? x0[(size_t)r * 256 + k] : h0[(size_t)r * UNITS + (k - 256)];
        __half hi = __float2half_rn(v);
        g_a0hi[idx] = hi;
        g_a0lo[idx] = __float2half_rn((v - __half2float(hi)) * LOSCALE);
    } else {
        int L = (blk - NB_WS - NB_W0 - NB_A0) * 256 + threadIdx.x;  // over BATCH*UNITS
        int mt = L >> 17;            // 64 nt * 2048 per m-tile
        int rem = L & 131071;
        int nt = rem >> 11;          // 2048 per n-tile
        int rem2 = rem & 2047;
        int etid = rem2 >> 4, pos = rem2 & 15;
        int ww = etid >> 4, q = etid & 15;
        int qr = q >> 1, th = q & 1;
        int wm = ww & 3, wn = ww >> 2;
        int mi = pos >> 3, half = (pos >> 2) & 1, nj = pos & 3;
        int r = mt * 128 + wm * 32 + mi * 16 + qr + half * 8;
        int u = nt * 16 + wn * 8 + nj * 2 + th;
        g_cf[L] = c0[(size_t)r * UNITS + u];
    }
}

// ------------------------------ fp32 prep GEMM -------------------------------
__global__ __launch_bounds__(256)
void sgemm128(const float* __restrict__ A, int lda,
              const float* __restrict__ B, int ldb, int K,
              const float* __restrict__ Cadd,
              float* __restrict__ C, int ldc) {
    __shared__ float As[8][128];
    __shared__ float Bs[8][128];
    const int tid = threadIdx.x;
    const int tx = tid & 15, ty = tid >> 4;
    const int row0 = blockIdx.y * 128, col0 = blockIdx.x * 128;
    float acc[8][8];
    #pragma unroll
    for (int i = 0; i < 8; ++i)
        #pragma unroll
        for (int j = 0; j < 8; ++j) acc[i][j] = 0.0f;
    const int arow = tid >> 1, acol = (tid & 1) << 2;
    const int brow = tid >> 5, bcol = (tid & 31) << 2;
    const float* Arow = A + (size_t)(row0 + arow) * lda + acol;
    const float* Brow = B + (size_t)brow * ldb + col0 + bcol;
    for (int k0 = 0; k0 < K; k0 += 8) {
        float4 av = *reinterpret_cast<const float4*>(Arow + k0);
        float4 bv = *reinterpret_cast<const float4*>(Brow + (size_t)k0 * ldb);
        As[acol + 0][arow] = av.x; As[acol + 1][arow] = av.y;
        As[acol + 2][arow] = av.z; As[acol + 3][arow] = av.w;
        *reinterpret_cast<float4*>(&Bs[brow][bcol]) = bv;
        __syncthreads();
        #pragma unroll
        for (int k = 0; k < 8; ++k) {
            float a[8], bb[8];
            #pragma unroll
            for (int i = 0; i < 8; ++i) a[i] = As[k][ty * 8 + i];
            #pragma unroll
            for (int j = 0; j < 8; ++j) bb[j] = Bs[k][tx * 8 + j];
            #pragma unroll
            for (int i = 0; i < 8; ++i)
                #pragma unroll
                for (int j = 0; j < 8; ++j)
                    acc[i][j] = fmaf(a[i], bb[j], acc[i][j]);
        }
        __syncthreads();
    }
    const int gcol = col0 + tx * 8;
    #pragma unroll
    for (int i = 0; i < 8; ++i) {
        int r = row0 + ty * 8 + i;
        #pragma unroll
        for (int j = 0; j < 8; j += 4) {
            float4 v = make_float4(acc[i][j], acc[i][j+1], acc[i][j+2], acc[i][j+3]);
            if (Cadd) {
                float4 a4 = *reinterpret_cast<const float4*>(Cadd + (size_t)r * ldb + gcol + j);
                v.x += a4.x; v.y += a4.y; v.z += a4.z; v.w += a4.w;
            }
            *reinterpret_cast<float4*>(C + (size_t)r * ldc + gcol + j) = v;
        }
    }
}

// ------------------------------ launch ---------------------------------------
extern "C" void kernel_launch(void* const* d_in, const int* in_sizes, int n_in,
                              void* d_out, int out_size) {
    const float* x0 = (const float*)d_in[0];
    const float* h0 = (const float*)d_in[1];
    const float* c0 = (const float*)d_in[2];
    const float* Wk = (const float*)d_in[3];
    const float* Wr = (const float*)d_in[4];
    const float* b  = (const float*)d_in[5];
    const float* Wd = (const float*)d_in[6];
    const float* bd = (const float*)d_in[7];
    float* out = (float*)d_out;

    cudaFuncSetAttribute(bgemm, cudaFuncAttributeMaxDynamicSharedMemorySize, SMEM_TOTAL);

    float *pWcd, *pBcd, *pB0i;
    __half *pWthi, *pWtlo, *pW0hi, *pW0lo, *pA0hi, *pA0lo;
    __half *pH0hi, *pH0lo, *pH1hi, *pH1lo;
    cudaGetSymbolAddress((void**)&pWcd, g_Wcd);
    cudaGetSymbolAddress((void**)&pBcd, g_bcd);
    cudaGetSymbolAddress((void**)&pB0i, g_b0i);
    cudaGetSymbolAddress((void**)&pWthi, g_wthi);
    cudaGetSymbolAddress((void**)&pWtlo, g_wtlo);
    cudaGetSymbolAddress((void**)&pW0hi, g_w0hi);
    cudaGetSymbolAddress((void**)&pW0lo, g_w0lo);
    cudaGetSymbolAddress((void**)&pA0hi, g_a0hi);
    cudaGetSymbolAddress((void**)&pA0lo, g_a0lo);
    cudaGetSymbolAddress((void**)&pH0hi, g_h0hi);
    cudaGetSymbolAddress((void**)&pH0lo, g_h0lo);
    cudaGetSymbolAddress((void**)&pH1hi, g_h1hi);
    cudaGetSymbolAddress((void**)&pH1lo, g_h1lo);

    // prep (3 kernels so ncu's fixed-index capture lands on bgemm)
    prep1<<<17 + 1024, 256>>>(b, bd, Wk, Wd);
    sgemm128<<<dim3(GATES / 128, UNITS / 128), 256>>>(
        Wd, OUTU, Wk, GATES, 256, Wr, pWcd, NCOMB);      // Wc = Wd@Wk + Wr
    prep_splits<<<NB_WS + NB_W0 + NB_A0 + NB_CI, 256>>>(Wk, Wr, x0, h0, c0);

    // h buffers: step t reads hb[t&1], writes hb[(t+1)&1]; step0 writes hb[1]
    __half* hhi[2] = {pH0hi, pH1hi};
    __half* hlo[2] = {pH0lo, pH1lo};

    // step 0: gates only (64 n-tiles), K=1280, fused LSTM -> h1
    bgemm<<<dim3(64, 16), 256, SMEM_TOTAL>>>(
        pA0hi, pA0lo, pW0hi, pW0lo, K0, pB0i, 0, 0, out, hhi[1], hlo[1]);

    // steps 1..95: gates + pred_{t-1} (68 n-tiles), K=1024
    for (int t = 1; t < STEPS; ++t) {
        bgemm<<<dim3(68, 16), 256, SMEM_TOTAL>>>(
            hhi[t & 1], hlo[t & 1], pWthi, pWtlo, UNITS, pBcd, 0, t, out,
            hhi[(t + 1) & 1], hlo[(t + 1) & 1]);
    }

    // final: pred_95 only (4 pred tiles), reads h_96 = hb[0]
    bgemm<<<dim3(4, 16), 256, SMEM_TOTAL>>>(
        hhi[0], hlo[0], pWthi, pWtlo, UNITS, pBcd, 64, STEPS, out,
        hhi[1], hlo[1]);
}

// round 10
// speedup vs baseline: 3.0696x; 1.3785x over previous
#include <cuda_runtime.h>
#include <cuda_fp16.h>
#include <cstdint>
#include <math.h>

#define BATCH 2048
#define UNITS 1024
#define GATES 4096
#define OUTU 256
#define NCOMB 4352            // [Wc | Wd]
#define STEPS 96
#define K0 1280               // step-0 K: [x | h]
#define LDO (STEPS * OUTU)
#define LOSCALE 2048.0f
#define INV_LOSCALE (1.0f / 2048.0f)

// ------------------------------ device scratch ------------------------------
__device__ __align__(256) float g_Wcd[UNITS * NCOMB];   // fp32 combined weights
__device__ __align__(256) float g_bcd[NCOMB];           // combined bias (gate-interleaved + pred)
__device__ __align__(256) float g_b0i[GATES];           // step0 bias (gate-interleaved)
__device__ __align__(256) float g_cf[BATCH * UNITS];    // cell state, FRAGMENT layout
__device__ __align__(256) __half g_h0[BATCH * UNITS];   // h ping-pong (plain fp16)
__device__ __align__(256) __half g_h1[BATCH * UNITS];
__device__ __align__(256) __half g_wthi[(size_t)NCOMB * UNITS];  // W^T hi, interleaved rows
__device__ __align__(256) __half g_wtlo[(size_t)NCOMB * UNITS];  // W^T lo*2048
__device__ __align__(256) __half g_w0hi[(size_t)GATES * K0];     // step0 W^T hi
__device__ __align__(256) __half g_w0lo[(size_t)GATES * K0];     // step0 W^T lo*2048
__device__ __align__(256) __half g_a0[(size_t)BATCH * K0];       // step0 A=[x|h] fp16

__device__ __forceinline__ int icol(int n) {            // gate interleave: unit*4+gate
    return (n < GATES) ? ((n & 1023) * 4 + (n >> 10)) : n;
}

// ------------------------------ PTX helpers ---------------------------------
__device__ __forceinline__ uint32_t smem_u32(const void* p) {
    uint32_t a;
    asm("{ .reg .u64 t; cvta.to.shared.u64 t, %1; cvt.u32.u64 %0, t; }" : "=r"(a) : "l"(p));
    return a;
}
__device__ __forceinline__ uint32_t swz(uint32_t off) { return off ^ ((off >> 3) & 0x70); }
__device__ __forceinline__ void cpa16(uint32_t dst, const void* src) {
    asm volatile("cp.async.cg.shared.global [%0], [%1], 16;" :: "r"(dst), "l"(src) : "memory");
}
#define CP_COMMIT()  asm volatile("cp.async.commit_group;" ::: "memory")
#define CP_WAIT(n)   asm volatile("cp.async.wait_group %0;" :: "n"(n) : "memory")

__device__ __forceinline__ void ldsm4(uint32_t* r, uint32_t addr) {
    asm volatile("ldmatrix.sync.aligned.m8n8.x4.shared.b16 {%0,%1,%2,%3}, [%4];"
        : "=r"(r[0]), "=r"(r[1]), "=r"(r[2]), "=r"(r[3]) : "r"(addr));
}
__device__ __forceinline__ void mma_f32(float* d, const uint32_t* a, uint32_t b0, uint32_t b1) {
    asm volatile("mma.sync.aligned.m16n8k16.row.col.f32.f16.f16.f32 "
        "{%0,%1,%2,%3}, {%4,%5,%6,%7}, {%8,%9}, {%0,%1,%2,%3};"
        : "+f"(d[0]), "+f"(d[1]), "+f"(d[2]), "+f"(d[3])
        : "r"(a[0]), "r"(a[1]), "r"(a[2]), "r"(a[3]), "r"(b0), "r"(b1));
}
__device__ __forceinline__ void mma_f16(uint32_t* d, const uint32_t* a, uint32_t b0, uint32_t b1) {
    asm volatile("mma.sync.aligned.m16n8k16.row.col.f16.f16.f16.f16 "
        "{%0,%1}, {%2,%3,%4,%5}, {%6,%7}, {%0,%1};"
        : "+r"(d[0]), "+r"(d[1])
        : "r"(a[0]), "r"(a[1]), "r"(a[2]), "r"(a[3]), "r"(b0), "r"(b1));
}

// ------------------------------ fused split-GEMM + LSTM ----------------------
// z = A(fp16) @ [Whi + Wlo/2048]^T : main fp32-acc + one fp16-acc correction.
// Tile 128(M)x64(N), 256 thr (4m x 2n warps, 32x32 each), KC=64,
// 3-stage cp.async pipeline (32KB/stage, 96KB/CTA -> 2 CTAs/SM),
// R4-validated skeleton: prefetch BEFORE wait, two syncs per chunk.
#define KC 64
#define OFF_AHI 0
#define OFF_BHI 16384
#define OFF_BLO 24576
#define STAGE_BYTES 32768
#define SMEM_TOTAL (3 * STAGE_BYTES)

__device__ __forceinline__ void load_chunk(
    uint32_t sb, int tid,
    const __half* __restrict__ a,
    const __half* __restrict__ bhi, const __half* __restrict__ blo,
    int r0, int n0, int K, int kc)
{
    const int kcol = kc * KC;
    #pragma unroll
    for (int i = 0; i < 4; ++i) {              // A: 128 rows x 8 chunks of 16B
        int q = tid + i * 256;
        int row = q >> 3, jj = q & 7;
        uint32_t so = swz(row * 128 + jj * 16);
        size_t ga = (size_t)(r0 + row) * K + kcol + jj * 8;
        cpa16(sb + OFF_AHI + so, a + ga);
    }
    #pragma unroll
    for (int i = 0; i < 2; ++i) {              // B: 64 rows x 8 chunks of 16B
        int q = tid + i * 256;
        int row = q >> 3, jj = q & 7;
        uint32_t so = swz(row * 128 + jj * 16);
        size_t gb = (size_t)(n0 + row) * K + kcol + jj * 8;
        cpa16(sb + OFF_BHI + so, bhi + gb);
        cpa16(sb + OFF_BLO + so, blo + gb);
    }
    CP_COMMIT();
}

__global__ __launch_bounds__(256, 2)
void bgemm(const __half* __restrict__ a,
           const __half* __restrict__ bhi, const __half* __restrict__ blo,
           int K, const float* __restrict__ bias, int n_tile_off, int t,
           float* __restrict__ outp, __half* __restrict__ hout)
{
    extern __shared__ __align__(1024) char smem[];
    const uint32_t sbase = smem_u32(smem);
    const int tid = threadIdx.x;
    const int lane = tid & 31, w = tid >> 5;
    const int wm = w & 3, wn = w >> 2;             // 4 (m) x 2 (n) warps
    const int r0 = blockIdx.y * 128;
    const int n0 = (blockIdx.x + n_tile_off) * 64;
    const int nch = K / KC;

    float dm[2][4][4];
    uint32_t dc[2][4][2];
    #pragma unroll
    for (int mi = 0; mi < 2; ++mi)
        #pragma unroll
        for (int nj = 0; nj < 4; ++nj) {
            #pragma unroll
            for (int q = 0; q < 4; ++q) dm[mi][nj][q] = 0.0f;
            dc[mi][nj][0] = 0u; dc[mi][nj][1] = 0u;
        }

    load_chunk(sbase + 0 * STAGE_BYTES, tid, a, bhi, blo, r0, n0, K, 0);
    load_chunk(sbase + 1 * STAGE_BYTES, tid, a, bhi, blo, r0, n0, K, 1);

    const int lr = lane & 7, sel = lane >> 3;

    for (int kc = 0; kc < nch; ++kc) {
        if (kc + 2 < nch) {
            load_chunk(sbase + ((kc + 2) % 3) * STAGE_BYTES, tid,
                       a, bhi, blo, r0, n0, K, kc + 2);
            CP_WAIT(2);
        } else if (kc + 1 < nch) {
            CP_WAIT(1);
        } else {
            CP_WAIT(0);
        }
        __syncthreads();
        const uint32_t sb = sbase + (kc % 3) * STAGE_BYTES;

        #pragma unroll
        for (int k16 = 0; k16 < 4; ++k16) {
            uint32_t ah[2][4], bh[2][4], bl[2][4];
            #pragma unroll
            for (int mi = 0; mi < 2; ++mi) {
                int row = wm * 32 + mi * 16 + lr + (sel & 1) * 8;
                int kbe = (k16 * 16 + (sel >> 1) * 8) * 2;
                ldsm4(ah[mi], sb + OFF_AHI + swz(row * 128 + kbe));
            }
            #pragma unroll
            for (int njp = 0; njp < 2; ++njp) {
                int nrow = wn * 32 + njp * 16 + lr + (sel >> 1) * 8;
                int kbe = (k16 * 16 + (sel & 1) * 8) * 2;
                uint32_t off = swz(nrow * 128 + kbe);
                ldsm4(bh[njp], sb + OFF_BHI + off);
                ldsm4(bl[njp], sb + OFF_BLO + off);
            }
            #pragma unroll
            for (int mi = 0; mi < 2; ++mi)
                #pragma unroll
                for (int nj = 0; nj < 4; ++nj)
                    mma_f32(dm[mi][nj], ah[mi],
                            bh[nj >> 1][(nj & 1) * 2], bh[nj >> 1][(nj & 1) * 2 + 1]);
            #pragma unroll
            for (int mi = 0; mi < 2; ++mi)
                #pragma unroll
                for (int nj = 0; nj < 4; ++nj)
                    mma_f16(dc[mi][nj], ah[mi],
                            bl[nj >> 1][(nj & 1) * 2], bl[nj >> 1][(nj & 1) * 2 + 1]);
        }
        __syncthreads();
    }

    // ---------------- epilogue ----------------
    const bool isPred = (n0 >= GATES);
    const int qr = lane >> 2, t4 = lane & 3, qc = t4 * 2;
    const bool evenT = ((t4 & 1) == 0);
    // fragment-layout c base (gate tiles only: blockIdx.x < 64)
    const int etid = w * 16 + qr * 2 + (t4 >> 1);            // [0,128)
    const size_t cbase =
        (((size_t)blockIdx.y * 64 + (size_t)blockIdx.x) * 128 + (size_t)etid) * 16;

    #pragma unroll
    for (int mi = 0; mi < 2; ++mi) {
        #pragma unroll
        for (int half = 0; half < 2; ++half) {
            const int r = r0 + wm * 32 + mi * 16 + qr + half * 8;
            float ca[4];
            if (!isPred && evenT)
                *reinterpret_cast<float4*>(ca) =
                    *reinterpret_cast<float4*>(g_cf + cbase + mi * 8 + half * 4);
            #pragma unroll
            for (int nj = 0; nj < 4; ++nj) {
                const int c = wn * 32 + nj * 8 + qc;
                __half2 hc = *reinterpret_cast<__half2*>(&dc[mi][nj][half]);
                float zx = dm[mi][nj][half * 2 + 0]
                         + INV_LOSCALE * __half2float(__low2half(hc)) + bias[n0 + c];
                float zy = dm[mi][nj][half * 2 + 1]
                         + INV_LOSCALE * __half2float(__high2half(hc)) + bias[n0 + c + 1];
                if (isPred) {
                    float2 v = make_float2(zx, zy);
                    *reinterpret_cast<float2*>(
                        outp + (size_t)r * LDO + (size_t)(t - 1) * OUTU + (n0 - GATES) + c) = v;
                } else {
                    // even t4 holds (zi,zf), odd holds (zg,zo) of the same unit
                    float ox = __shfl_xor_sync(0xffffffffu, zx, 1);
                    float oy = __shfl_xor_sync(0xffffffffu, zy, 1);
                    if (evenT) {
                        const int u = ((n0 + c) >> 2);
                        const size_t off = (size_t)r * UNITS + u;
                        float ig = 1.0f / (1.0f + expf(-zx));
                        float fg = 1.0f / (1.0f + expf(-zy));
                        float gg = tanhf(ox);
                        float og = 1.0f / (1.0f + expf(-oy));
                        float cn = fg * ca[nj] + ig * gg;
                        ca[nj] = cn;
                        hout[off] = __float2half_rn(og * tanhf(cn));
                    }
                }
            }
            if (!isPred && evenT)
                *reinterpret_cast<float4*>(g_cf + cbase + mi * 8 + half * 4) =
                    *reinterpret_cast<float4*>(ca);
        }
    }
}

// ------------------------------ merged prep 1 --------------------------------
__global__ void prep1(const float* __restrict__ b, const float* __restrict__ bd,
                      const float* __restrict__ Wk, const float* __restrict__ Wd) {
    int blk = blockIdx.x;
    if (blk < 17) {
        int j = blk * 256 + threadIdx.x;
        if (j < GATES) {
            float s = b[j];
            #pragma unroll 4
            for (int k = 0; k < 256; ++k)
                s += bd[k] * Wk[(size_t)k * GATES + j];
            g_bcd[icol(j)] = s;
            g_b0i[icol(j)] = b[j];
        } else if (j < NCOMB) {
            g_bcd[j] = bd[j - GATES];
        }
    } else {
        int idx = (blk - 17) * 256 + threadIdx.x;
        if (idx < UNITS * OUTU) {
            int r = idx / OUTU, c = idx % OUTU;
            g_Wcd[(size_t)r * NCOMB + GATES + c] = Wd[idx];
        }
    }
}

// ------------------------------ merged prep splits ---------------------------
// [0, NB_WS): wsplit | [.., +NB_W0): w0split | [.., +NB_A0): a0 (fp16 only)
// [.., +NB_CI): c_init (canonical c0 -> fragment layout, 128x64 tiles)
#define NB_WS 17408
#define NB_W0 20480
#define NB_A0 10240
#define NB_CI 8192
__global__ void prep_splits(const float* __restrict__ Wk, const float* __restrict__ Wr,
                            const float* __restrict__ x0, const float* __restrict__ h0,
                            const float* __restrict__ c0) {
    int blk = blockIdx.x;
    if (blk < NB_WS) {
        int idx = blk * 256 + threadIdx.x;            // over UNITS*NCOMB
        int k = idx / NCOMB, n = idx - k * NCOMB;
        float v = g_Wcd[idx];
        __half hi = __float2half_rn(v);
        size_t o = (size_t)icol(n) * UNITS + k;
        g_wthi[o] = hi;
        g_wtlo[o] = __float2half_rn((v - __half2float(hi)) * LOSCALE);
    } else if (blk < NB_WS + NB_W0) {
        int idx = (blk - NB_WS) * 256 + threadIdx.x;  // over GATES*K0
        int n = idx & (GATES - 1);
        int k = idx >> 12;
        float v = (k < 256) ? Wk[(size_t)k * GATES + n]
                            : Wr[(size_t)(k - 256) * GATES + n];
        __half hi = __float2half_rn(v);
        size_t o = (size_t)icol(n) * K0 + k;
        g_w0hi[o] = hi;
        g_w0lo[o] = __float2half_rn((v - __half2float(hi)) * LOSCALE);
    } else if (blk < NB_WS + NB_W0 + NB_A0) {
        int idx = (blk - NB_WS - NB_W0) * 256 + threadIdx.x;  // over BATCH*K0
        int r = idx / K0, k = idx - r * K0;
        float v = (k < 256) ? x0[(size_t)r * 256 + k] : h0[(size_t)r * UNITS + (k - 256)];
        g_a0[idx] = __float2half_rn(v);
    } else {
        int L = (blk - NB_WS - NB_W0 - NB_A0) * 256 + threadIdx.x;  // over BATCH*UNITS
        int mt = L >> 17;            // 64 nt * 2048 per m-tile
        int rem = L & 131071;
        int nt = rem >> 11;          // 2048 per n-tile
        int rem2 = rem & 2047;
        int etid = rem2 >> 4, pos = rem2 & 15;
        int ww = etid >> 4, q = etid & 15;
        int qr = q >> 1, th = q & 1;
        int wm = ww & 3, wn = ww >> 2;
        int mi = pos >> 3, half = (pos >> 2) & 1, nj = pos & 3;
        int r = mt * 128 + wm * 32 + mi * 16 + qr + half * 8;
        int u = nt * 16 + wn * 8 + nj * 2 + th;
        g_cf[L] = c0[(size_t)r * UNITS + u];
    }
}

// ------------------------------ fp32 prep GEMM -------------------------------
__global__ __launch_bounds__(256)
void sgemm128(const float* __restrict__ A, int lda,
              const float* __restrict__ B, int ldb, int K,
              const float* __restrict__ Cadd,
              float* __restrict__ C, int ldc) {
    __shared__ float As[8][128];
    __shared__ float Bs[8][128];
    const int tid = threadIdx.x;
    const int tx = tid & 15, ty = tid >> 4;
    const int row0 = blockIdx.y * 128, col0 = blockIdx.x * 128;
    float acc[8][8];
    #pragma unroll
    for (int i = 0; i < 8; ++i)
        #pragma unroll
        for (int j = 0; j < 8; ++j) acc[i][j] = 0.0f;
    const int arow = tid >> 1, acol = (tid & 1) << 2;
    const int brow = tid >> 5, bcol = (tid & 31) << 2;
    const float* Arow = A + (size_t)(row0 + arow) * lda + acol;
    const float* Brow = B + (size_t)brow * ldb + col0 + bcol;
    for (int k0 = 0; k0 < K; k0 += 8) {
        float4 av = *reinterpret_cast<const float4*>(Arow + k0);
        float4 bv = *reinterpret_cast<const float4*>(Brow + (size_t)k0 * ldb);
        As[acol + 0][arow] = av.x; As[acol + 1][arow] = av.y;
        As[acol + 2][arow] = av.z; As[acol + 3][arow] = av.w;
        *reinterpret_cast<float4*>(&Bs[brow][bcol]) = bv;
        __syncthreads();
        #pragma unroll
        for (int k = 0; k < 8; ++k) {
            float a[8], bb[8];
            #pragma unroll
            for (int i = 0; i < 8; ++i) a[i] = As[k][ty * 8 + i];
            #pragma unroll
            for (int j = 0; j < 8; ++j) bb[j] = Bs[k][tx * 8 + j];
            #pragma unroll
            for (int i = 0; i < 8; ++i)
                #pragma unroll
                for (int j = 0; j < 8; ++j)
                    acc[i][j] = fmaf(a[i], bb[j], acc[i][j]);
        }
        __syncthreads();
    }
    const int gcol = col0 + tx * 8;
    #pragma unroll
    for (int i = 0; i < 8; ++i) {
        int r = row0 + ty * 8 + i;
        #pragma unroll
        for (int j = 0; j < 8; j += 4) {
            float4 v = make_float4(acc[i][j], acc[i][j+1], acc[i][j+2], acc[i][j+3]);
            if (Cadd) {
                float4 a4 = *reinterpret_cast<const float4*>(Cadd + (size_t)r * ldb + gcol + j);
                v.x += a4.x; v.y += a4.y; v.z += a4.z; v.w += a4.w;
            }
            *reinterpret_cast<float4*>(C + (size_t)r * ldc + gcol + j) = v;
        }
    }
}

// ------------------------------ launch ---------------------------------------
extern "C" void kernel_launch(void* const* d_in, const int* in_sizes, int n_in,
                              void* d_out, int out_size) {
    const float* x0 = (const float*)d_in[0];
    const float* h0 = (const float*)d_in[1];
    const float* c0 = (const float*)d_in[2];
    const float* Wk = (const float*)d_in[3];
    const float* Wr = (const float*)d_in[4];
    const float* b  = (const float*)d_in[5];
    const float* Wd = (const float*)d_in[6];
    const float* bd = (const float*)d_in[7];
    float* out = (float*)d_out;

    cudaFuncSetAttribute(bgemm, cudaFuncAttributeMaxDynamicSharedMemorySize, SMEM_TOTAL);

    float *pWcd;
    __half *pWthi, *pWtlo, *pW0hi, *pW0lo, *pA0, *pH0, *pH1;
    float *pBcd, *pB0i;
    cudaGetSymbolAddress((void**)&pWcd, g_Wcd);
    cudaGetSymbolAddress((void**)&pBcd, g_bcd);
    cudaGetSymbolAddress((void**)&pB0i, g_b0i);
    cudaGetSymbolAddress((void**)&pWthi, g_wthi);
    cudaGetSymbolAddress((void**)&pWtlo, g_wtlo);
    cudaGetSymbolAddress((void**)&pW0hi, g_w0hi);
    cudaGetSymbolAddress((void**)&pW0lo, g_w0lo);
    cudaGetSymbolAddress((void**)&pA0, g_a0);
    cudaGetSymbolAddress((void**)&pH0, g_h0);
    cudaGetSymbolAddress((void**)&pH1, g_h1);

    // prep (3 kernels so ncu's fixed-index capture lands on bgemm)
    prep1<<<17 + 1024, 256>>>(b, bd, Wk, Wd);
    sgemm128<<<dim3(GATES / 128, UNITS / 128), 256>>>(
        Wd, OUTU, Wk, GATES, 256, Wr, pWcd, NCOMB);      // Wc = Wd@Wk + Wr
    prep_splits<<<NB_WS + NB_W0 + NB_A0 + NB_CI, 256>>>(Wk, Wr, x0, h0, c0);

    // h buffers: step t reads hb[t&1], writes hb[(t+1)&1]; step0 writes hb[1]
    __half* hb[2] = {pH0, pH1};

    // step 0: gates only (64 n-tiles), K=1280, fused LSTM -> h1
    bgemm<<<dim3(64, 16), 256, SMEM_TOTAL>>>(
        pA0, pW0hi, pW0lo, K0, pB0i, 0, 0, out, hb[1]);

    // steps 1..95: gates + pred_{t-1} (68 n-tiles), K=1024
    for (int t = 1; t < STEPS; ++t) {
        bgemm<<<dim3(68, 16), 256, SMEM_TOTAL>>>(
            hb[t & 1], pWthi, pWtlo, UNITS, pBcd, 0, t, out, hb[(t + 1) & 1]);
    }

    // final: pred_95 only (4 pred tiles), reads h_96 = hb[0]
    bgemm<<<dim3(4, 16), 256, SMEM_TOTAL>>>(
        hb[0], pWthi, pWtlo, UNITS, pBcd, 64, STEPS, out, hb[1]);
}